// round 1
// baseline (speedup 1.0000x reference)
#include <cuda_runtime.h>
#include <cstdint>

// ---------------------------------------------------------------------------
// Decoder: x[8,512,8,8], style[8,512]
//  5 x { upsample2x -> modconv3x3 -> relu }  then final conv3x3 + bias
// Key trick: upsample2x + conv3x3(pad1) == per-parity 2x2 conv on the SOURCE
// grid. Weights precombined into wc[co][ci][parity(4)][tap(4)].
// ---------------------------------------------------------------------------

#define B_ 8

// ---- static scratch (no allocations allowed) ----
__device__ float g_a1[B_ * 256 * 16 * 16];
__device__ float g_a2[B_ * 128 * 32 * 32];
__device__ float g_a3[B_ * 64 * 64 * 64];
__device__ float g_a4[B_ * 64 * 128 * 128];
__device__ float g_a5[B_ * 64 * 256 * 256];

__device__ float g_wc1[256 * 512 * 16];
__device__ float g_wc2[128 * 256 * 16];
__device__ float g_wc3[64 * 128 * 16];
__device__ float g_wc4[64 * 64 * 16];
__device__ float g_wc5[64 * 64 * 16];

__device__ float g_s1[B_ * 256];
__device__ float g_s2[B_ * 128];
__device__ float g_s3[B_ * 64];
__device__ float g_s4[B_ * 64];
__device__ float g_s5[B_ * 64];

// ---------------------------------------------------------------------------
// Style FC: s[b][o] = dot(style[b,:512], fw[o,:512]) + fb[o]
// one warp per (b,o)
// ---------------------------------------------------------------------------
__global__ void style_fc(const float* __restrict__ style,
                         const float* __restrict__ fw,
                         const float* __restrict__ fb,
                         float* __restrict__ s, int O) {
    int warp = (blockIdx.x * blockDim.x + threadIdx.x) >> 5;
    int lane = threadIdx.x & 31;
    int total = B_ * O;
    if (warp >= total) return;
    int b = warp / O, o = warp % O;
    const float* st = style + b * 512;
    const float* wp = fw + (size_t)o * 512;
    float acc = 0.f;
#pragma unroll 4
    for (int i = lane; i < 512; i += 32) acc += st[i] * wp[i];
#pragma unroll
    for (int off = 16; off > 0; off >>= 1)
        acc += __shfl_down_sync(0xffffffffu, acc, off);
    if (lane == 0) s[warp] = acc + fb[o];
}

// ---------------------------------------------------------------------------
// Combine 3x3 weights into parity 2x2 weights.
// parity p = py*2+px. tap index = a*2+bb.
//   rows: py==0 : a0 <- {ky0},     a1 <- {ky1,ky2}   (src iy = m-1+a)
//         py==1 : a0 <- {ky0,ky1}, a1 <- {ky2}       (src iy = m+a)
//   cols likewise with px / kx.
// ---------------------------------------------------------------------------
__global__ void combine_w(const float* __restrict__ w, float* __restrict__ wc,
                          int n /* = CO*CI */) {
    int i = blockIdx.x * blockDim.x + threadIdx.x;
    if (i >= n) return;
    const float* wp = w + (size_t)i * 9;
    float a[3][3];
#pragma unroll
    for (int ky = 0; ky < 3; ky++)
#pragma unroll
        for (int kx = 0; kx < 3; kx++) a[ky][kx] = wp[ky * 3 + kx];

    // column combine: cc[ky][px][b]
    float cc[3][2][2];
#pragma unroll
    for (int ky = 0; ky < 3; ky++) {
        cc[ky][0][0] = a[ky][0];
        cc[ky][0][1] = a[ky][1] + a[ky][2];
        cc[ky][1][0] = a[ky][0] + a[ky][1];
        cc[ky][1][1] = a[ky][2];
    }
    float out[16];
#pragma unroll
    for (int py = 0; py < 2; py++)
#pragma unroll
        for (int px = 0; px < 2; px++)
#pragma unroll
            for (int aa = 0; aa < 2; aa++)
#pragma unroll
                for (int bb = 0; bb < 2; bb++) {
                    float v;
                    if (py == 0)
                        v = (aa == 0) ? cc[0][px][bb] : cc[1][px][bb] + cc[2][px][bb];
                    else
                        v = (aa == 0) ? cc[0][px][bb] + cc[1][px][bb] : cc[2][px][bb];
                    out[(py * 2 + px) * 4 + aa * 2 + bb] = v;
                }
    float* o = wc + (size_t)i * 16;
#pragma unroll
    for (int k = 0; k < 16; k++) o[k] = out[k];
}

// ---------------------------------------------------------------------------
// Fused upsample2x + 3x3 conv + style-scale + relu.
// Each thread: COT(=4) output channels, CTH(=2) vertical source centers,
// each center -> 2x2 output pixels.  32 fp32 accumulators.
// Block: (32, 4) = 128 threads.  32 lanes cover LANES_W columns x
// (32/LANES_W) center rows; threadIdx.y selects a group of COT channels.
// ---------------------------------------------------------------------------
template <int CI, int CO, int HS, int WS, int LANES_W>
__global__ void __launch_bounds__(128)
upconv(const float* __restrict__ src, const float* __restrict__ wc,
       const float* __restrict__ sc, float* __restrict__ dst) {
    constexpr int COT = 4;
    constexpr int CTH = 2;
    constexpr int RPW = 32 / LANES_W;          // center rows per 32 lanes
    constexpr int M_PER_BLOCK = RPW * CTH;
    constexpr int HO = 2 * HS, WO = 2 * WS;

    const int lane = threadIdx.x;
    const int n = blockIdx.x * LANES_W + (lane % LANES_W);
    const int m_base = blockIdx.y * M_PER_BLOCK + (lane / LANES_W) * CTH;
    constexpr int GROUPS = CO / (COT * 4);
    const int b = blockIdx.z / GROUPS;
    const int cg = blockIdx.z % GROUPS;
    const int co0 = (cg * 4 + threadIdx.y) * COT;

    float acc[COT][CTH][4];
#pragma unroll
    for (int t = 0; t < COT; t++)
#pragma unroll
        for (int c = 0; c < CTH; c++)
#pragma unroll
            for (int p = 0; p < 4; p++) acc[t][c][p] = 0.f;

    const float* srcb = src + (size_t)b * CI * HS * WS;

    for (int ci = 0; ci < CI; ci++) {
        // source patch rows m_base-1 .. m_base+CTH, cols n-1 .. n+1
        float xv[CTH + 2][3];
        const float* sp = srcb + (size_t)ci * HS * WS;
#pragma unroll
        for (int r = 0; r < CTH + 2; r++) {
            int iy = m_base - 1 + r;
            bool vy = (iy >= 0) && (iy < HS);
#pragma unroll
            for (int c = 0; c < 3; c++) {
                int ix = n - 1 + c;
                bool v = vy && (ix >= 0) && (ix < WS);
                xv[r][c] = v ? sp[iy * WS + ix] : 0.f;
            }
        }
#pragma unroll
        for (int t = 0; t < COT; t++) {
            const float4* wp = reinterpret_cast<const float4*>(
                wc + (((size_t)(co0 + t) * CI + ci) << 4));
            float4 wA = wp[0], wB = wp[1], wC = wp[2], wD = wp[3];
            float w[16] = {wA.x, wA.y, wA.z, wA.w, wB.x, wB.y, wB.z, wB.w,
                           wC.x, wC.y, wC.z, wC.w, wD.x, wD.y, wD.z, wD.w};
#pragma unroll
            for (int ct = 0; ct < CTH; ct++)
#pragma unroll
                for (int py = 0; py < 2; py++)
#pragma unroll
                    for (int px = 0; px < 2; px++) {
                        const int p = py * 2 + px;
#pragma unroll
                        for (int aa = 0; aa < 2; aa++)
#pragma unroll
                            for (int bb = 0; bb < 2; bb++)
                                acc[t][ct][p] = fmaf(w[p * 4 + aa * 2 + bb],
                                                     xv[ct + aa + py][bb + px],
                                                     acc[t][ct][p]);
                    }
        }
    }

    // epilogue: scale, relu, store
#pragma unroll
    for (int t = 0; t < COT; t++) {
        const int co = co0 + t;
        const float sv = sc[b * CO + co];
        float* dp = dst + (((size_t)b * CO + co) * HO) * WO;
#pragma unroll
        for (int ct = 0; ct < CTH; ct++) {
            const int m = m_base + ct;
#pragma unroll
            for (int py = 0; py < 2; py++)
#pragma unroll
                for (int px = 0; px < 2; px++) {
                    float v = acc[t][ct][py * 2 + px] * sv;
                    v = v > 0.f ? v : 0.f;
                    dp[(2 * m + py) * WO + (2 * n + px)] = v;
                }
        }
    }
}

// ---------------------------------------------------------------------------
// Final plain 3x3 conv: 64 -> 3 channels, 256x256, + bias. Each thread: 2x2
// pixels x 3 channels. Weights staged in smem.
// ---------------------------------------------------------------------------
__global__ void __launch_bounds__(256)
final_conv(const float* __restrict__ src, const float* __restrict__ wf,
           const float* __restrict__ bf, float* __restrict__ dst) {
    constexpr int H = 256, W = 256, CI = 64;
    __shared__ float ws[3 * 64 * 9];
    for (int i = threadIdx.x; i < 3 * 64 * 9; i += blockDim.x) ws[i] = wf[i];
    __syncthreads();

    const int b = blockIdx.z;
    const int tx = threadIdx.x % 16, ty = threadIdx.x / 16;
    const int px0 = blockIdx.x * 32 + tx * 2;
    const int py0 = blockIdx.y * 32 + ty * 2;

    float acc[3][4];
#pragma unroll
    for (int c = 0; c < 3; c++)
#pragma unroll
        for (int p = 0; p < 4; p++) acc[c][p] = 0.f;

    const float* srcb = src + (size_t)b * CI * H * W;
    for (int ci = 0; ci < CI; ci++) {
        float xv[4][4];
        const float* sp = srcb + (size_t)ci * H * W;
#pragma unroll
        for (int r = 0; r < 4; r++) {
            int iy = py0 - 1 + r;
            bool vy = (iy >= 0) && (iy < H);
#pragma unroll
            for (int c = 0; c < 4; c++) {
                int ix = px0 - 1 + c;
                bool v = vy && (ix >= 0) && (ix < W);
                xv[r][c] = v ? sp[iy * W + ix] : 0.f;
            }
        }
#pragma unroll
        for (int co = 0; co < 3; co++) {
            const float* wsp = ws + co * (64 * 9) + ci * 9;
#pragma unroll
            for (int ky = 0; ky < 3; ky++)
#pragma unroll
                for (int kx = 0; kx < 3; kx++) {
                    float w = wsp[ky * 3 + kx];
#pragma unroll
                    for (int dy = 0; dy < 2; dy++)
#pragma unroll
                        for (int dx = 0; dx < 2; dx++)
                            acc[co][dy * 2 + dx] =
                                fmaf(w, xv[dy + ky][dx + kx], acc[co][dy * 2 + dx]);
                }
        }
    }
#pragma unroll
    for (int co = 0; co < 3; co++) {
        float bias = bf[co];
        float* dp = dst + (((size_t)b * 3 + co) * H) * W;
#pragma unroll
        for (int dy = 0; dy < 2; dy++)
#pragma unroll
            for (int dx = 0; dx < 2; dx++)
                dp[(py0 + dy) * W + (px0 + dx)] = acc[co][dy * 2 + dx] + bias;
    }
}

// ---------------------------------------------------------------------------
// launch
// ---------------------------------------------------------------------------
static void* sym(const void* s) {
    void* p = nullptr;
    cudaGetSymbolAddress(&p, s);
    return p;
}

extern "C" void kernel_launch(void* const* d_in, const int* in_sizes, int n_in,
                              void* d_out, int out_size) {
    const float* x     = (const float*)d_in[0];
    const float* style = (const float*)d_in[1];
    const float* w1 = (const float*)d_in[2];
    const float* fw1 = (const float*)d_in[3];
    const float* fb1 = (const float*)d_in[4];
    const float* w2 = (const float*)d_in[5];
    const float* fw2 = (const float*)d_in[6];
    const float* fb2 = (const float*)d_in[7];
    const float* w3 = (const float*)d_in[8];
    const float* fw3 = (const float*)d_in[9];
    const float* fb3 = (const float*)d_in[10];
    const float* w4 = (const float*)d_in[11];
    const float* fw4 = (const float*)d_in[12];
    const float* fb4 = (const float*)d_in[13];
    const float* w5 = (const float*)d_in[14];
    const float* fw5 = (const float*)d_in[15];
    const float* fb5 = (const float*)d_in[16];
    const float* wf = (const float*)d_in[17];
    const float* bf = (const float*)d_in[18];

    float* a1 = (float*)sym(g_a1);
    float* a2 = (float*)sym(g_a2);
    float* a3 = (float*)sym(g_a3);
    float* a4 = (float*)sym(g_a4);
    float* a5 = (float*)sym(g_a5);
    float* wc1 = (float*)sym(g_wc1);
    float* wc2 = (float*)sym(g_wc2);
    float* wc3 = (float*)sym(g_wc3);
    float* wc4 = (float*)sym(g_wc4);
    float* wc5 = (float*)sym(g_wc5);
    float* s1 = (float*)sym(g_s1);
    float* s2 = (float*)sym(g_s2);
    float* s3 = (float*)sym(g_s3);
    float* s4 = (float*)sym(g_s4);
    float* s5 = (float*)sym(g_s5);

    // --- weight precombine ---
    auto cw = [](const float* w, float* wc, int n) {
        combine_w<<<(n + 255) / 256, 256>>>(w, wc, n);
    };
    cw(w1, wc1, 256 * 512);
    cw(w2, wc2, 128 * 256);
    cw(w3, wc3, 64 * 128);
    cw(w4, wc4, 64 * 64);
    cw(w5, wc5, 64 * 64);

    // --- style scales ---
    auto st = [&](const float* fw, const float* fb, float* s, int O) {
        int warps = B_ * O;
        style_fc<<<(warps * 32 + 255) / 256, 256>>>(style, fw, fb, s, O);
    };
    st(fw1, fb1, s1, 256);
    st(fw2, fb2, s2, 128);
    st(fw3, fb3, s3, 64);
    st(fw4, fb4, s4, 64);
    st(fw5, fb5, s5, 64);

    dim3 blk(32, 4, 1);
    // L1: 512->256, 8x8 src -> 16x16
    upconv<512, 256, 8, 8, 8><<<dim3(1, 1, B_ * (256 / 16)), blk>>>(x, wc1, s1, a1);
    // L2: 256->128, 16 -> 32
    upconv<256, 128, 16, 16, 16><<<dim3(1, 4, B_ * (128 / 16)), blk>>>(a1, wc2, s2, a2);
    // L3: 128->64, 32 -> 64
    upconv<128, 64, 32, 32, 32><<<dim3(1, 16, B_ * (64 / 16)), blk>>>(a2, wc3, s3, a3);
    // L4: 64->64, 64 -> 128
    upconv<64, 64, 64, 64, 32><<<dim3(2, 32, B_ * (64 / 16)), blk>>>(a3, wc4, s4, a4);
    // L5: 64->64, 128 -> 256
    upconv<64, 64, 128, 128, 32><<<dim3(4, 64, B_ * (64 / 16)), blk>>>(a4, wc5, s5, a5);

    // final conv 64 -> 3 + bias
    final_conv<<<dim3(8, 8, B_), 256>>>(a5, wf, bf, (float*)d_out);
}

// round 5
// speedup vs baseline: 1.1628x; 1.1628x over previous
#include <cuda_runtime.h>
#include <cstdint>

// ---------------------------------------------------------------------------
// Decoder: x[8,512,8,8], style[8,512]
//  5 x { upsample2x -> modconv3x3 -> relu }  then final conv3x3 + bias
// upsample2x + conv3x3(pad1) == per-parity 2x2 conv on the SOURCE grid.
// Weights precombined into wc[co][ci][parity(4)][tap(4)].
// v2: smem-staged source tiles (double buffered, ci-chunked), per-layer
// tuned tiling, fused prologue kernels, float2 stores.
// ---------------------------------------------------------------------------

#define B_ 8

// ---- static scratch (no allocations allowed) ----
__device__ float g_a1[B_ * 256 * 16 * 16];
__device__ float g_a2[B_ * 128 * 32 * 32];
__device__ float g_a3[B_ * 64 * 64 * 64];
__device__ float g_a4[B_ * 64 * 128 * 128];
__device__ float g_a5[B_ * 64 * 256 * 256];

__device__ float g_wc1[256 * 512 * 16];
__device__ float g_wc2[128 * 256 * 16];
__device__ float g_wc3[64 * 128 * 16];
__device__ float g_wc4[64 * 64 * 16];
__device__ float g_wc5[64 * 64 * 16];

__device__ float g_s1[B_ * 256];
__device__ float g_s2[B_ * 128];
__device__ float g_s3[B_ * 64];
__device__ float g_s4[B_ * 64];
__device__ float g_s5[B_ * 64];

// ---------------------------------------------------------------------------
// Fused style FC for all 5 layers: one warp per (b, concat-output)
// concat outputs per batch: 256 + 128 + 64 + 64 + 64 = 576
// ---------------------------------------------------------------------------
__global__ void style_all(const float* __restrict__ style,
                          const float* __restrict__ fw1, const float* __restrict__ fb1, float* __restrict__ s1,
                          const float* __restrict__ fw2, const float* __restrict__ fb2, float* __restrict__ s2,
                          const float* __restrict__ fw3, const float* __restrict__ fb3, float* __restrict__ s3,
                          const float* __restrict__ fw4, const float* __restrict__ fb4, float* __restrict__ s4,
                          const float* __restrict__ fw5, const float* __restrict__ fb5, float* __restrict__ s5) {
    int warp = (blockIdx.x * blockDim.x + threadIdx.x) >> 5;
    int lane = threadIdx.x & 31;
    if (warp >= B_ * 576) return;
    int b = warp / 576;
    int o = warp % 576;
    const float *fw, *fb;
    float* s;
    int O, lo;
    if (o < 256)      { fw = fw1; fb = fb1; s = s1; O = 256; lo = o; }
    else if (o < 384) { fw = fw2; fb = fb2; s = s2; O = 128; lo = o - 256; }
    else if (o < 448) { fw = fw3; fb = fb3; s = s3; O = 64;  lo = o - 384; }
    else if (o < 512) { fw = fw4; fb = fb4; s = s4; O = 64;  lo = o - 448; }
    else              { fw = fw5; fb = fb5; s = s5; O = 64;  lo = o - 512; }
    const float* st = style + b * 512;
    const float* wp = fw + (size_t)lo * 512;
    float acc = 0.f;
#pragma unroll 4
    for (int i = lane; i < 512; i += 32) acc += st[i] * wp[i];
#pragma unroll
    for (int off = 16; off > 0; off >>= 1)
        acc += __shfl_down_sync(0xffffffffu, acc, off);
    if (lane == 0) s[b * O + lo] = acc + fb[lo];
}

// ---------------------------------------------------------------------------
// Fused weight precombine for all 5 layers.
// thread i handles one (co,ci) filter of one layer (segments by range).
// ---------------------------------------------------------------------------
__device__ __forceinline__ void combine_one(const float* __restrict__ wp,
                                            float* __restrict__ o) {
    float a[3][3];
#pragma unroll
    for (int ky = 0; ky < 3; ky++)
#pragma unroll
        for (int kx = 0; kx < 3; kx++) a[ky][kx] = wp[ky * 3 + kx];
    float cc[3][2][2];
#pragma unroll
    for (int ky = 0; ky < 3; ky++) {
        cc[ky][0][0] = a[ky][0];
        cc[ky][0][1] = a[ky][1] + a[ky][2];
        cc[ky][1][0] = a[ky][0] + a[ky][1];
        cc[ky][1][1] = a[ky][2];
    }
#pragma unroll
    for (int py = 0; py < 2; py++)
#pragma unroll
        for (int px = 0; px < 2; px++)
#pragma unroll
            for (int aa = 0; aa < 2; aa++)
#pragma unroll
                for (int bb = 0; bb < 2; bb++) {
                    float v;
                    if (py == 0)
                        v = (aa == 0) ? cc[0][px][bb] : cc[1][px][bb] + cc[2][px][bb];
                    else
                        v = (aa == 0) ? cc[0][px][bb] + cc[1][px][bb] : cc[2][px][bb];
                    o[(py * 2 + px) * 4 + aa * 2 + bb] = v;
                }
}

#define N1 (256 * 512)
#define N2 (128 * 256)
#define N3 (64 * 128)
#define N4 (64 * 64)
#define N5 (64 * 64)

__global__ void combine_all(const float* __restrict__ w1, float* __restrict__ wc1,
                            const float* __restrict__ w2, float* __restrict__ wc2,
                            const float* __restrict__ w3, float* __restrict__ wc3,
                            const float* __restrict__ w4, float* __restrict__ wc4,
                            const float* __restrict__ w5, float* __restrict__ wc5) {
    int i = blockIdx.x * blockDim.x + threadIdx.x;
    const float* w;
    float* wc;
    int li;
    if (i < N1)                          { w = w1; wc = wc1; li = i; }
    else if (i < N1 + N2)                { w = w2; wc = wc2; li = i - N1; }
    else if (i < N1 + N2 + N3)           { w = w3; wc = wc3; li = i - N1 - N2; }
    else if (i < N1 + N2 + N3 + N4)      { w = w4; wc = wc4; li = i - N1 - N2 - N3; }
    else if (i < N1 + N2 + N3 + N4 + N5) { w = w5; wc = wc5; li = i - N1 - N2 - N3 - N4; }
    else return;
    combine_one(w + (size_t)li * 9, wc + (size_t)li * 16);
}

// ---------------------------------------------------------------------------
// Fused upsample2x + 3x3 conv + style-scale + relu, smem-staged.
// Block: (32, YG). 32 lanes cover LANES_W cols x (32/LANES_W)*CTH center
// rows; threadIdx.y picks a group of COT output channels.
// Source tile (with halo) for a chunk of 8 ci is staged in smem (double
// buffered) and shared by all YG channel groups.
// ---------------------------------------------------------------------------
template <int CI, int CO, int HS, int WS, int LANES_W, int COT, int YG>
__global__ void __launch_bounds__(32 * YG)
upconv(const float* __restrict__ src, const float* __restrict__ wc,
       const float* __restrict__ sc, float* __restrict__ dst) {
    constexpr int CTH = 2;
    constexpr int RPW = 32 / LANES_W;
    constexpr int MPB = RPW * CTH;                // center rows per block
    constexpr int HO = 2 * HS, WO = 2 * WS;
    constexpr int TR = MPB + 2;                   // tile rows (with halo)
    constexpr int TCP = (LANES_W == 32) ? 34 : (LANES_W == 16 ? 24 : 12);
    constexpr int CHUNK = 8;
    constexpr int NTH = 32 * YG;
    constexpr int TILE = CHUNK * TR * TCP;
    constexpr int GROUPS = CO / (COT * YG);
    constexpr int NC = CI / CHUNK;

    __shared__ float sbuf[2][TILE];

    const int lane = threadIdx.x;
    const int tid = threadIdx.y * 32 + lane;
    const int nl = lane % LANES_W;                // local col (center grid)
    const int ml = (lane / LANES_W) * CTH;        // local center row
    const int col0 = blockIdx.x * LANES_W;
    const int row0 = blockIdx.y * MPB;
    const int n = col0 + nl;
    const int b = blockIdx.z / GROUPS;
    const int cg = blockIdx.z % GROUPS;
    const int co0 = (cg * YG + threadIdx.y) * COT;
    const int m_base = row0 + ml;

    const float* srcb = src + (size_t)b * CI * HS * WS;

    float acc[COT][CTH][4];
#pragma unroll
    for (int t = 0; t < COT; t++)
#pragma unroll
        for (int c = 0; c < CTH; c++)
#pragma unroll
            for (int p = 0; p < 4; p++) acc[t][c][p] = 0.f;

    // cooperative tile loader: tile row 0 = row0-1, tile col 0 = col0-1
    auto load_chunk = [&](float* buf, int ci0) {
#pragma unroll 2
        for (int idx = tid; idx < TILE; idx += NTH) {
            int cc = idx / (TR * TCP);
            int rem = idx % (TR * TCP);
            int r = rem / TCP, c = rem % TCP;
            int iy = row0 - 1 + r;
            int ix = col0 - 1 + c;
            float v = 0.f;
            if (iy >= 0 && iy < HS && ix >= 0 && ix < WS)
                v = srcb[(size_t)(ci0 + cc) * HS * WS + iy * WS + ix];
            buf[idx] = v;
        }
    };

    load_chunk(sbuf[0], 0);
    __syncthreads();

    for (int k = 0; k < NC; k++) {
        const float* cur = sbuf[k & 1];
        if (k + 1 < NC) load_chunk(sbuf[(k + 1) & 1], (k + 1) * CHUNK);
        const int ci0 = k * CHUNK;
#pragma unroll
        for (int ccI = 0; ccI < CHUNK; ccI++) {
            const float* tp = cur + ccI * TR * TCP;
            float xv[CTH + 2][3];
#pragma unroll
            for (int r = 0; r < CTH + 2; r++)
#pragma unroll
                for (int c = 0; c < 3; c++)
                    xv[r][c] = tp[(ml + r) * TCP + nl + c];
            const int ci = ci0 + ccI;
#pragma unroll
            for (int t = 0; t < COT; t++) {
                const float4* wp = reinterpret_cast<const float4*>(
                    wc + (((size_t)(co0 + t) * CI + ci) << 4));
                float4 wA = wp[0], wB = wp[1], wC = wp[2], wD = wp[3];
                float w[16] = {wA.x, wA.y, wA.z, wA.w, wB.x, wB.y, wB.z, wB.w,
                               wC.x, wC.y, wC.z, wC.w, wD.x, wD.y, wD.z, wD.w};
#pragma unroll
                for (int ct = 0; ct < CTH; ct++)
#pragma unroll
                    for (int py = 0; py < 2; py++)
#pragma unroll
                        for (int px = 0; px < 2; px++) {
                            const int p = py * 2 + px;
#pragma unroll
                            for (int aa = 0; aa < 2; aa++)
#pragma unroll
                                for (int bb = 0; bb < 2; bb++)
                                    acc[t][ct][p] = fmaf(w[p * 4 + aa * 2 + bb],
                                                         xv[ct + aa + py][bb + px],
                                                         acc[t][ct][p]);
                        }
            }
        }
        __syncthreads();
    }

    // epilogue: scale, relu, float2 store
#pragma unroll
    for (int t = 0; t < COT; t++) {
        const int co = co0 + t;
        const float sv = sc[b * CO + co];
        float* dp = dst + (((size_t)b * CO + co) * HO) * WO;
#pragma unroll
        for (int ct = 0; ct < CTH; ct++) {
            const int m = m_base + ct;
#pragma unroll
            for (int py = 0; py < 2; py++) {
                float v0 = acc[t][ct][py * 2 + 0] * sv;
                float v1 = acc[t][ct][py * 2 + 1] * sv;
                v0 = v0 > 0.f ? v0 : 0.f;
                v1 = v1 > 0.f ? v1 : 0.f;
                *reinterpret_cast<float2*>(dp + (2 * m + py) * WO + 2 * n) =
                    make_float2(v0, v1);
            }
        }
    }
}

// ---------------------------------------------------------------------------
// Final plain 3x3 conv: 64 -> 3 channels, 256x256, + bias, smem staged.
// Block 256 thr = 16x16, each thread 2x2 px x 3 channels (32x32 out tile).
// ---------------------------------------------------------------------------
__global__ void __launch_bounds__(256)
final_conv(const float* __restrict__ src, const float* __restrict__ wf,
           const float* __restrict__ bf, float* __restrict__ dst) {
    constexpr int H = 256, W = 256, CI = 64;
    constexpr int TCP = 34;
    constexpr int TR = 34;
    constexpr int CHUNK = 2;
    constexpr int TILE = CHUNK * TR * TCP;
    constexpr int NC = CI / CHUNK;

    __shared__ float ws[3 * 64 * 9];
    __shared__ float xs[2][TILE];

    const int tid = threadIdx.x;
    for (int i = tid; i < 3 * 64 * 9; i += 256) ws[i] = wf[i];

    const int b = blockIdx.z;
    const int tx = tid % 16, ty = tid / 16;
    const int col0 = blockIdx.x * 32;
    const int row0 = blockIdx.y * 32;
    const int px0 = col0 + tx * 2;
    const int py0 = row0 + ty * 2;

    const float* srcb = src + (size_t)b * CI * H * W;

    auto load_chunk = [&](float* buf, int ci0) {
#pragma unroll 2
        for (int idx = tid; idx < TILE; idx += 256) {
            int cc = idx / (TR * TCP);
            int rem = idx % (TR * TCP);
            int r = rem / TCP, c = rem % TCP;
            int iy = row0 - 1 + r;
            int ix = col0 - 1 + c;
            float v = 0.f;
            if (iy >= 0 && iy < H && ix >= 0 && ix < W)
                v = srcb[(size_t)(ci0 + cc) * H * W + iy * W + ix];
            buf[idx] = v;
        }
    };

    float acc[3][4];
#pragma unroll
    for (int c = 0; c < 3; c++)
#pragma unroll
        for (int p = 0; p < 4; p++) acc[c][p] = 0.f;

    load_chunk(xs[0], 0);
    __syncthreads();

    for (int k = 0; k < NC; k++) {
        const float* cur = xs[k & 1];
        if (k + 1 < NC) load_chunk(xs[(k + 1) & 1], (k + 1) * CHUNK);
        const int ci0 = k * CHUNK;
#pragma unroll
        for (int ccI = 0; ccI < CHUNK; ccI++) {
            const float* tp = cur + ccI * TR * TCP;
            float xv[4][4];
#pragma unroll
            for (int r = 0; r < 4; r++)
#pragma unroll
                for (int c = 0; c < 4; c++)
                    xv[r][c] = tp[(ty * 2 + r) * TCP + tx * 2 + c];
            const int ci = ci0 + ccI;
#pragma unroll
            for (int co = 0; co < 3; co++) {
                const float* wsp = ws + co * (64 * 9) + ci * 9;
#pragma unroll
                for (int ky = 0; ky < 3; ky++)
#pragma unroll
                    for (int kx = 0; kx < 3; kx++) {
                        float w = wsp[ky * 3 + kx];
#pragma unroll
                        for (int dy = 0; dy < 2; dy++)
#pragma unroll
                            for (int dx = 0; dx < 2; dx++)
                                acc[co][dy * 2 + dx] =
                                    fmaf(w, xv[dy + ky][dx + kx], acc[co][dy * 2 + dx]);
                    }
            }
        }
        __syncthreads();
    }

#pragma unroll
    for (int co = 0; co < 3; co++) {
        float bias = bf[co];
        float* dp = dst + (((size_t)b * 3 + co) * H) * W;
#pragma unroll
        for (int dy = 0; dy < 2; dy++) {
            float v0 = acc[co][dy * 2 + 0] + bias;
            float v1 = acc[co][dy * 2 + 1] + bias;
            *reinterpret_cast<float2*>(dp + (py0 + dy) * W + px0) =
                make_float2(v0, v1);
        }
    }
}

// ---------------------------------------------------------------------------
// launch
// ---------------------------------------------------------------------------
static void* sym(const void* s) {
    void* p = nullptr;
    cudaGetSymbolAddress(&p, s);
    return p;
}

extern "C" void kernel_launch(void* const* d_in, const int* in_sizes, int n_in,
                              void* d_out, int out_size) {
    const float* x     = (const float*)d_in[0];
    const float* style = (const float*)d_in[1];
    const float* w1 = (const float*)d_in[2];
    const float* fw1 = (const float*)d_in[3];
    const float* fb1 = (const float*)d_in[4];
    const float* w2 = (const float*)d_in[5];
    const float* fw2 = (const float*)d_in[6];
    const float* fb2 = (const float*)d_in[7];
    const float* w3 = (const float*)d_in[8];
    const float* fw3 = (const float*)d_in[9];
    const float* fb3 = (const float*)d_in[10];
    const float* w4 = (const float*)d_in[11];
    const float* fw4 = (const float*)d_in[12];
    const float* fb4 = (const float*)d_in[13];
    const float* w5 = (const float*)d_in[14];
    const float* fw5 = (const float*)d_in[15];
    const float* fb5 = (const float*)d_in[16];
    const float* wf = (const float*)d_in[17];
    const float* bf = (const float*)d_in[18];

    float* a1 = (float*)sym(g_a1);
    float* a2 = (float*)sym(g_a2);
    float* a3 = (float*)sym(g_a3);
    float* a4 = (float*)sym(g_a4);
    float* a5 = (float*)sym(g_a5);
    float* wc1 = (float*)sym(g_wc1);
    float* wc2 = (float*)sym(g_wc2);
    float* wc3 = (float*)sym(g_wc3);
    float* wc4 = (float*)sym(g_wc4);
    float* wc5 = (float*)sym(g_wc5);
    float* s1 = (float*)sym(g_s1);
    float* s2 = (float*)sym(g_s2);
    float* s3 = (float*)sym(g_s3);
    float* s4 = (float*)sym(g_s4);
    float* s5 = (float*)sym(g_s5);

    // fused prologue (2 launches instead of 10)
    {
        int ntot = N1 + N2 + N3 + N4 + N5;
        combine_all<<<(ntot + 255) / 256, 256>>>(w1, wc1, w2, wc2, w3, wc3,
                                                 w4, wc4, w5, wc5);
        int warps = B_ * 576;
        style_all<<<(warps * 32 + 255) / 256, 256>>>(style,
                                                     fw1, fb1, s1, fw2, fb2, s2,
                                                     fw3, fb3, s3, fw4, fb4, s4,
                                                     fw5, fb5, s5);
    }

    // L1: 512->256, 8x8 -> 16x16.  256 thr, COT=2, YG=8 (co/block=16)
    upconv<512, 256, 8, 8, 8, 2, 8><<<dim3(1, 1, B_ * 16), dim3(32, 8)>>>(x, wc1, s1, a1);
    // L2: 256->128, 16 -> 32.  256 thr, COT=4, YG=8 (co/block=32)
    upconv<256, 128, 16, 16, 16, 4, 8><<<dim3(1, 4, B_ * 4), dim3(32, 8)>>>(a1, wc2, s2, a2);
    // L3: 128->64, 32 -> 64.  128 thr, COT=4, YG=4 (co/block=16)
    upconv<128, 64, 32, 32, 32, 4, 4><<<dim3(1, 16, B_ * 4), dim3(32, 4)>>>(a2, wc3, s3, a3);
    // L4: 64->64, 64 -> 128
    upconv<64, 64, 64, 64, 32, 4, 4><<<dim3(2, 32, B_ * 4), dim3(32, 4)>>>(a3, wc4, s4, a4);
    // L5: 64->64, 128 -> 256
    upconv<64, 64, 128, 128, 32, 4, 4><<<dim3(4, 64, B_ * 4), dim3(32, 4)>>>(a4, wc5, s5, a5);

    // final conv 64 -> 3 + bias
    final_conv<<<dim3(8, 8, B_), 256>>>(a5, wf, bf, (float*)d_out);
}

// round 6
// speedup vs baseline: 1.6391x; 1.4097x over previous
#include <cuda_runtime.h>
#include <cstdint>

// ---------------------------------------------------------------------------
// Decoder: x[8,512,8,8], style[8,512]
//  5 x { upsample2x -> modconv3x3 -> relu }  then final conv3x3 + bias
// upsample2x + conv3x3(pad1) == per-parity 2x2 conv on the SOURCE grid.
// Weights precombined into wc[co][ci][parity(4)][tap(4)].
// v3: BOTH x tiles and weight tiles staged in smem (double buffered,
// ci-chunked) so the inner loop is pure LDS+FFMA; retuned grids.
// ---------------------------------------------------------------------------

#define B_ 8

// ---- static scratch (no allocations allowed) ----
__device__ float g_a1[B_ * 256 * 16 * 16];
__device__ float g_a2[B_ * 128 * 32 * 32];
__device__ float g_a3[B_ * 64 * 64 * 64];
__device__ float g_a4[B_ * 64 * 128 * 128];
__device__ float g_a5[B_ * 64 * 256 * 256];

__device__ float g_wc1[256 * 512 * 16];
__device__ float g_wc2[128 * 256 * 16];
__device__ float g_wc3[64 * 128 * 16];
__device__ float g_wc4[64 * 64 * 16];
__device__ float g_wc5[64 * 64 * 16];

__device__ float g_s1[B_ * 256];
__device__ float g_s2[B_ * 128];
__device__ float g_s3[B_ * 64];
__device__ float g_s4[B_ * 64];
__device__ float g_s5[B_ * 64];

// ---------------------------------------------------------------------------
// Fused style FC for all 5 layers: one warp per (b, concat-output)
// ---------------------------------------------------------------------------
__global__ void style_all(const float* __restrict__ style,
                          const float* __restrict__ fw1, const float* __restrict__ fb1, float* __restrict__ s1,
                          const float* __restrict__ fw2, const float* __restrict__ fb2, float* __restrict__ s2,
                          const float* __restrict__ fw3, const float* __restrict__ fb3, float* __restrict__ s3,
                          const float* __restrict__ fw4, const float* __restrict__ fb4, float* __restrict__ s4,
                          const float* __restrict__ fw5, const float* __restrict__ fb5, float* __restrict__ s5) {
    int warp = (blockIdx.x * blockDim.x + threadIdx.x) >> 5;
    int lane = threadIdx.x & 31;
    if (warp >= B_ * 576) return;
    int b = warp / 576;
    int o = warp % 576;
    const float *fw, *fb;
    float* s;
    int O, lo;
    if (o < 256)      { fw = fw1; fb = fb1; s = s1; O = 256; lo = o; }
    else if (o < 384) { fw = fw2; fb = fb2; s = s2; O = 128; lo = o - 256; }
    else if (o < 448) { fw = fw3; fb = fb3; s = s3; O = 64;  lo = o - 384; }
    else if (o < 512) { fw = fw4; fb = fb4; s = s4; O = 64;  lo = o - 448; }
    else              { fw = fw5; fb = fb5; s = s5; O = 64;  lo = o - 512; }
    const float* st = style + b * 512;
    const float* wp = fw + (size_t)lo * 512;
    float acc = 0.f;
#pragma unroll 4
    for (int i = lane; i < 512; i += 32) acc += st[i] * wp[i];
#pragma unroll
    for (int off = 16; off > 0; off >>= 1)
        acc += __shfl_down_sync(0xffffffffu, acc, off);
    if (lane == 0) s[b * O + lo] = acc + fb[lo];
}

// ---------------------------------------------------------------------------
// Fused weight precombine for all 5 layers.
// ---------------------------------------------------------------------------
__device__ __forceinline__ void combine_one(const float* __restrict__ wp,
                                            float* __restrict__ o) {
    float a[3][3];
#pragma unroll
    for (int ky = 0; ky < 3; ky++)
#pragma unroll
        for (int kx = 0; kx < 3; kx++) a[ky][kx] = wp[ky * 3 + kx];
    float cc[3][2][2];
#pragma unroll
    for (int ky = 0; ky < 3; ky++) {
        cc[ky][0][0] = a[ky][0];
        cc[ky][0][1] = a[ky][1] + a[ky][2];
        cc[ky][1][0] = a[ky][0] + a[ky][1];
        cc[ky][1][1] = a[ky][2];
    }
#pragma unroll
    for (int py = 0; py < 2; py++)
#pragma unroll
        for (int px = 0; px < 2; px++)
#pragma unroll
            for (int aa = 0; aa < 2; aa++)
#pragma unroll
                for (int bb = 0; bb < 2; bb++) {
                    float v;
                    if (py == 0)
                        v = (aa == 0) ? cc[0][px][bb] : cc[1][px][bb] + cc[2][px][bb];
                    else
                        v = (aa == 0) ? cc[0][px][bb] + cc[1][px][bb] : cc[2][px][bb];
                    o[(py * 2 + px) * 4 + aa * 2 + bb] = v;
                }
}

#define N1 (256 * 512)
#define N2 (128 * 256)
#define N3 (64 * 128)
#define N4 (64 * 64)
#define N5 (64 * 64)

__global__ void combine_all(const float* __restrict__ w1, float* __restrict__ wc1,
                            const float* __restrict__ w2, float* __restrict__ wc2,
                            const float* __restrict__ w3, float* __restrict__ wc3,
                            const float* __restrict__ w4, float* __restrict__ wc4,
                            const float* __restrict__ w5, float* __restrict__ wc5) {
    int i = blockIdx.x * blockDim.x + threadIdx.x;
    const float* w;
    float* wc;
    int li;
    if (i < N1)                          { w = w1; wc = wc1; li = i; }
    else if (i < N1 + N2)                { w = w2; wc = wc2; li = i - N1; }
    else if (i < N1 + N2 + N3)           { w = w3; wc = wc3; li = i - N1 - N2; }
    else if (i < N1 + N2 + N3 + N4)      { w = w4; wc = wc4; li = i - N1 - N2 - N3; }
    else if (i < N1 + N2 + N3 + N4 + N5) { w = w5; wc = wc5; li = i - N1 - N2 - N3 - N4; }
    else return;
    combine_one(w + (size_t)li * 9, wc + (size_t)li * 16);
}

// ---------------------------------------------------------------------------
// Fused upsample2x + 3x3 conv + style-scale + relu.
// Block: (32, YG). 32 lanes cover LANES_W cols x (32/LANES_W)*CTH center
// rows; threadIdx.y picks a group of COT output channels.
// BOTH the source tile (with halo) and the weight tile for each chunk of 8
// ci are staged in smem, double buffered: inner loop is pure LDS + FFMA.
// ---------------------------------------------------------------------------
template <int CI, int CO, int HS, int WS, int LANES_W, int COT, int YG>
__global__ void __launch_bounds__(32 * YG)
upconv(const float* __restrict__ src, const float* __restrict__ wc,
       const float* __restrict__ sc, float* __restrict__ dst) {
    constexpr int CTH = 2;
    constexpr int RPW = 32 / LANES_W;
    constexpr int MPB = RPW * CTH;                // center rows per block
    constexpr int HO = 2 * HS, WO = 2 * WS;
    constexpr int TR = MPB + 2;                   // tile rows (with halo)
    constexpr int TCP = (LANES_W == 32) ? 34 : (LANES_W == 16 ? 24 : 12);
    constexpr int CHUNK = 8;
    constexpr int NTH = 32 * YG;
    constexpr int TILE = CHUNK * TR * TCP;        // x-tile floats
    constexpr int COB = YG * COT;                 // out channels per block
    constexpr int WTILE = CHUNK * COB * 16;       // weight-tile floats
    constexpr int GROUPS = CO / COB;
    constexpr int NC = CI / CHUNK;

    __shared__ float sbuf[2][TILE];
    __shared__ float wbuf[2][WTILE];

    const int lane = threadIdx.x;
    const int tid = threadIdx.y * 32 + lane;
    const int nl = lane % LANES_W;                // local col (center grid)
    const int ml = (lane / LANES_W) * CTH;        // local center row
    const int col0 = blockIdx.x * LANES_W;
    const int row0 = blockIdx.y * MPB;
    const int n = col0 + nl;
    const int b = blockIdx.z / GROUPS;
    const int cg = blockIdx.z % GROUPS;
    const int co_blk = cg * COB;
    const int co0 = co_blk + threadIdx.y * COT;
    const int m_base = row0 + ml;

    const float* srcb = src + (size_t)b * CI * HS * WS;

    float acc[COT][CTH][4];
#pragma unroll
    for (int t = 0; t < COT; t++)
#pragma unroll
        for (int c = 0; c < CTH; c++)
#pragma unroll
            for (int p = 0; p < 4; p++) acc[t][c][p] = 0.f;

    // cooperative x-tile loader: tile row 0 = row0-1, tile col 0 = col0-1
    auto load_x = [&](float* buf, int ci0) {
#pragma unroll 2
        for (int idx = tid; idx < TILE; idx += NTH) {
            int cc = idx / (TR * TCP);
            int rem = idx % (TR * TCP);
            int r = rem / TCP, c = rem % TCP;
            int iy = row0 - 1 + r;
            int ix = col0 - 1 + c;
            float v = 0.f;
            if (iy >= 0 && iy < HS && ix >= 0 && ix < WS)
                v = srcb[(size_t)(ci0 + cc) * HS * WS + iy * WS + ix];
            buf[idx] = v;
        }
    };

    // cooperative weight-tile loader (float4 granularity)
    // smem layout: [cc][j][16] with j in [0, COB)
    auto load_w = [&](float* buf, int ci0) {
#pragma unroll 2
        for (int idx = tid; idx < WTILE / 4; idx += NTH) {
            int k4 = idx & 3;
            int rest = idx >> 2;
            int j = rest % COB;
            int cc = rest / COB;
            float4 v = *reinterpret_cast<const float4*>(
                wc + (((size_t)(co_blk + j) * CI + ci0 + cc) << 4) + k4 * 4);
            reinterpret_cast<float4*>(buf)[idx] = v;
        }
    };

    load_x(sbuf[0], 0);
    load_w(wbuf[0], 0);
    __syncthreads();

    for (int k = 0; k < NC; k++) {
        const float* curx = sbuf[k & 1];
        const float* curw = wbuf[k & 1];
        if (k + 1 < NC) {
            load_x(sbuf[(k + 1) & 1], (k + 1) * CHUNK);
            load_w(wbuf[(k + 1) & 1], (k + 1) * CHUNK);
        }
#pragma unroll
        for (int ccI = 0; ccI < CHUNK; ccI++) {
            const float* tp = curx + ccI * TR * TCP;
            float xv[CTH + 2][3];
#pragma unroll
            for (int r = 0; r < CTH + 2; r++)
#pragma unroll
                for (int c = 0; c < 3; c++)
                    xv[r][c] = tp[(ml + r) * TCP + nl + c];
#pragma unroll
            for (int t = 0; t < COT; t++) {
                const float4* wp4 = reinterpret_cast<const float4*>(curw) +
                                    (ccI * COB + threadIdx.y * COT + t) * 4;
                float4 wA = wp4[0], wB = wp4[1], wC = wp4[2], wD = wp4[3];
                float w[16] = {wA.x, wA.y, wA.z, wA.w, wB.x, wB.y, wB.z, wB.w,
                               wC.x, wC.y, wC.z, wC.w, wD.x, wD.y, wD.z, wD.w};
#pragma unroll
                for (int ct = 0; ct < CTH; ct++)
#pragma unroll
                    for (int py = 0; py < 2; py++)
#pragma unroll
                        for (int px = 0; px < 2; px++) {
                            const int p = py * 2 + px;
#pragma unroll
                            for (int aa = 0; aa < 2; aa++)
#pragma unroll
                                for (int bb = 0; bb < 2; bb++)
                                    acc[t][ct][p] = fmaf(w[p * 4 + aa * 2 + bb],
                                                         xv[ct + aa + py][bb + px],
                                                         acc[t][ct][p]);
                        }
            }
        }
        __syncthreads();
    }

    // epilogue: scale, relu, float2 store
#pragma unroll
    for (int t = 0; t < COT; t++) {
        const int co = co0 + t;
        const float sv = sc[b * CO + co];
        float* dp = dst + (((size_t)b * CO + co) * HO) * WO;
#pragma unroll
        for (int ct = 0; ct < CTH; ct++) {
            const int m = m_base + ct;
#pragma unroll
            for (int py = 0; py < 2; py++) {
                float v0 = acc[t][ct][py * 2 + 0] * sv;
                float v1 = acc[t][ct][py * 2 + 1] * sv;
                v0 = v0 > 0.f ? v0 : 0.f;
                v1 = v1 > 0.f ? v1 : 0.f;
                *reinterpret_cast<float2*>(dp + (2 * m + py) * WO + 2 * n) =
                    make_float2(v0, v1);
            }
        }
    }
}

// ---------------------------------------------------------------------------
// Final plain 3x3 conv: 64 -> 3 channels, 256x256, + bias, smem staged.
// ---------------------------------------------------------------------------
__global__ void __launch_bounds__(256)
final_conv(const float* __restrict__ src, const float* __restrict__ wf,
           const float* __restrict__ bf, float* __restrict__ dst) {
    constexpr int H = 256, W = 256, CI = 64;
    constexpr int TCP = 34;
    constexpr int TR = 34;
    constexpr int CHUNK = 2;
    constexpr int TILE = CHUNK * TR * TCP;
    constexpr int NC = CI / CHUNK;

    __shared__ float ws[3 * 64 * 9];
    __shared__ float xs[2][TILE];

    const int tid = threadIdx.x;
    for (int i = tid; i < 3 * 64 * 9; i += 256) ws[i] = wf[i];

    const int b = blockIdx.z;
    const int tx = tid % 16, ty = tid / 16;
    const int col0 = blockIdx.x * 32;
    const int row0 = blockIdx.y * 32;
    const int px0 = col0 + tx * 2;
    const int py0 = row0 + ty * 2;

    const float* srcb = src + (size_t)b * CI * H * W;

    auto load_chunk = [&](float* buf, int ci0) {
#pragma unroll 2
        for (int idx = tid; idx < TILE; idx += 256) {
            int cc = idx / (TR * TCP);
            int rem = idx % (TR * TCP);
            int r = rem / TCP, c = rem % TCP;
            int iy = row0 - 1 + r;
            int ix = col0 - 1 + c;
            float v = 0.f;
            if (iy >= 0 && iy < H && ix >= 0 && ix < W)
                v = srcb[(size_t)(ci0 + cc) * H * W + iy * W + ix];
            buf[idx] = v;
        }
    };

    float acc[3][4];
#pragma unroll
    for (int c = 0; c < 3; c++)
#pragma unroll
        for (int p = 0; p < 4; p++) acc[c][p] = 0.f;

    load_chunk(xs[0], 0);
    __syncthreads();

    for (int k = 0; k < NC; k++) {
        const float* cur = xs[k & 1];
        if (k + 1 < NC) load_chunk(xs[(k + 1) & 1], (k + 1) * CHUNK);
        const int ci0 = k * CHUNK;
#pragma unroll
        for (int ccI = 0; ccI < CHUNK; ccI++) {
            const float* tp = cur + ccI * TR * TCP;
            float xv[4][4];
#pragma unroll
            for (int r = 0; r < 4; r++)
#pragma unroll
                for (int c = 0; c < 4; c++)
                    xv[r][c] = tp[(ty * 2 + r) * TCP + tx * 2 + c];
            const int ci = ci0 + ccI;
#pragma unroll
            for (int co = 0; co < 3; co++) {
                const float* wsp = ws + co * (64 * 9) + ci * 9;
#pragma unroll
                for (int ky = 0; ky < 3; ky++)
#pragma unroll
                    for (int kx = 0; kx < 3; kx++) {
                        float w = wsp[ky * 3 + kx];
#pragma unroll
                        for (int dy = 0; dy < 2; dy++)
#pragma unroll
                            for (int dx = 0; dx < 2; dx++)
                                acc[co][dy * 2 + dx] =
                                    fmaf(w, xv[dy + ky][dx + kx], acc[co][dy * 2 + dx]);
                    }
            }
        }
        __syncthreads();
    }

#pragma unroll
    for (int co = 0; co < 3; co++) {
        float bias = bf[co];
        float* dp = dst + (((size_t)b * 3 + co) * H) * W;
#pragma unroll
        for (int dy = 0; dy < 2; dy++) {
            float v0 = acc[co][dy * 2 + 0] + bias;
            float v1 = acc[co][dy * 2 + 1] + bias;
            *reinterpret_cast<float2*>(dp + (py0 + dy) * W + px0) =
                make_float2(v0, v1);
        }
    }
}

// ---------------------------------------------------------------------------
// launch
// ---------------------------------------------------------------------------
static void* sym(const void* s) {
    void* p = nullptr;
    cudaGetSymbolAddress(&p, s);
    return p;
}

extern "C" void kernel_launch(void* const* d_in, const int* in_sizes, int n_in,
                              void* d_out, int out_size) {
    const float* x     = (const float*)d_in[0];
    const float* style = (const float*)d_in[1];
    const float* w1 = (const float*)d_in[2];
    const float* fw1 = (const float*)d_in[3];
    const float* fb1 = (const float*)d_in[4];
    const float* w2 = (const float*)d_in[5];
    const float* fw2 = (const float*)d_in[6];
    const float* fb2 = (const float*)d_in[7];
    const float* w3 = (const float*)d_in[8];
    const float* fw3 = (const float*)d_in[9];
    const float* fb3 = (const float*)d_in[10];
    const float* w4 = (const float*)d_in[11];
    const float* fw4 = (const float*)d_in[12];
    const float* fb4 = (const float*)d_in[13];
    const float* w5 = (const float*)d_in[14];
    const float* fw5 = (const float*)d_in[15];
    const float* fb5 = (const float*)d_in[16];
    const float* wf = (const float*)d_in[17];
    const float* bf = (const float*)d_in[18];

    float* a1 = (float*)sym(g_a1);
    float* a2 = (float*)sym(g_a2);
    float* a3 = (float*)sym(g_a3);
    float* a4 = (float*)sym(g_a4);
    float* a5 = (float*)sym(g_a5);
    float* wc1 = (float*)sym(g_wc1);
    float* wc2 = (float*)sym(g_wc2);
    float* wc3 = (float*)sym(g_wc3);
    float* wc4 = (float*)sym(g_wc4);
    float* wc5 = (float*)sym(g_wc5);
    float* s1 = (float*)sym(g_s1);
    float* s2 = (float*)sym(g_s2);
    float* s3 = (float*)sym(g_s3);
    float* s4 = (float*)sym(g_s4);
    float* s5 = (float*)sym(g_s5);

    // fused prologue
    {
        int ntot = N1 + N2 + N3 + N4 + N5;
        combine_all<<<(ntot + 255) / 256, 256>>>(w1, wc1, w2, wc2, w3, wc3,
                                                 w4, wc4, w5, wc5);
        int warps = B_ * 576;
        style_all<<<(warps * 32 + 255) / 256, 256>>>(style,
                                                     fw1, fb1, s1, fw2, fb2, s2,
                                                     fw3, fb3, s3, fw4, fb4, s4,
                                                     fw5, fb5, s5);
    }

    // L1: 512->256, 8x8 -> 16x16.  256 thr, COT=2, YG=8 (16 co/block, 128 blocks)
    upconv<512, 256, 8, 8, 8, 2, 8><<<dim3(1, 1, B_ * 16), dim3(32, 8)>>>(x, wc1, s1, a1);
    // L2: 256->128, 16 -> 32.  256 thr, COT=2, YG=8 (16 co/block, 256 blocks)
    upconv<256, 128, 16, 16, 16, 2, 8><<<dim3(1, 4, B_ * 8), dim3(32, 8)>>>(a1, wc2, s2, a2);
    // L3: 128->64, 32 -> 64.  128 thr, COT=4, YG=4 (512 blocks)
    upconv<128, 64, 32, 32, 32, 4, 4><<<dim3(1, 16, B_ * 4), dim3(32, 4)>>>(a2, wc3, s3, a3);
    // L4: 64->64, 64 -> 128  (2048 blocks)
    upconv<64, 64, 64, 64, 32, 4, 4><<<dim3(2, 32, B_ * 4), dim3(32, 4)>>>(a3, wc4, s4, a4);
    // L5: 64->64, 128 -> 256  (8192 blocks)
    upconv<64, 64, 128, 128, 32, 4, 4><<<dim3(4, 64, B_ * 4), dim3(32, 4)>>>(a4, wc5, s5, a5);

    // final conv 64 -> 3 + bias
    final_conv<<<dim3(8, 8, B_), 256>>>(a5, wf, bf, (float*)d_out);
}

// round 7
// speedup vs baseline: 1.6949x; 1.0340x over previous
#include <cuda_runtime.h>
#include <cstdint>

// ---------------------------------------------------------------------------
// Decoder: x[8,512,8,8], style[8,512]
//  5 x { upsample2x -> modconv3x3 -> relu }  then final conv3x3 + bias
// upsample2x + conv3x3(pad1) == per-parity 2x2 conv on the SOURCE grid.
// v4: packed fp32 math via PTX fma.rn.f32x2 (FFMA2). Combined weights are
// stored px-interleaved: wc[co][ci][py][aa][bb] = float2(w_px0, w_px1), so
// the packed weight operand comes straight from shared memory.
// ---------------------------------------------------------------------------

#define B_ 8

// ---- static scratch (no allocations allowed) ----
__device__ float g_a1[B_ * 256 * 16 * 16];
__device__ float g_a2[B_ * 128 * 32 * 32];
__device__ float g_a3[B_ * 64 * 64 * 64];
__device__ float g_a4[B_ * 64 * 128 * 128];
__device__ float g_a5[B_ * 64 * 256 * 256];

__device__ float g_wc1[256 * 512 * 16];
__device__ float g_wc2[128 * 256 * 16];
__device__ float g_wc3[64 * 128 * 16];
__device__ float g_wc4[64 * 64 * 16];
__device__ float g_wc5[64 * 64 * 16];

__device__ float g_s1[B_ * 256];
__device__ float g_s2[B_ * 128];
__device__ float g_s3[B_ * 64];
__device__ float g_s4[B_ * 64];
__device__ float g_s5[B_ * 64];

// ---- packed f32x2 helpers ----
__device__ __forceinline__ unsigned long long pack2(float lo, float hi) {
    unsigned long long r;
    asm("mov.b64 %0, {%1, %2};" : "=l"(r) : "f"(lo), "f"(hi));
    return r;
}
__device__ __forceinline__ void unpack2(unsigned long long v, float& lo, float& hi) {
    asm("mov.b64 {%0, %1}, %2;" : "=f"(lo), "=f"(hi) : "l"(v));
}
__device__ __forceinline__ void fma2(unsigned long long& d, unsigned long long a,
                                     unsigned long long b) {
    asm("fma.rn.f32x2 %0, %1, %2, %0;" : "+l"(d) : "l"(a), "l"(b));
}

// ---------------------------------------------------------------------------
// Fused style FC for all 5 layers: one warp per (b, concat-output)
// ---------------------------------------------------------------------------
__global__ void style_all(const float* __restrict__ style,
                          const float* __restrict__ fw1, const float* __restrict__ fb1, float* __restrict__ s1,
                          const float* __restrict__ fw2, const float* __restrict__ fb2, float* __restrict__ s2,
                          const float* __restrict__ fw3, const float* __restrict__ fb3, float* __restrict__ s3,
                          const float* __restrict__ fw4, const float* __restrict__ fb4, float* __restrict__ s4,
                          const float* __restrict__ fw5, const float* __restrict__ fb5, float* __restrict__ s5) {
    int warp = (blockIdx.x * blockDim.x + threadIdx.x) >> 5;
    int lane = threadIdx.x & 31;
    if (warp >= B_ * 576) return;
    int b = warp / 576;
    int o = warp % 576;
    const float *fw, *fb;
    float* s;
    int O, lo;
    if (o < 256)      { fw = fw1; fb = fb1; s = s1; O = 256; lo = o; }
    else if (o < 384) { fw = fw2; fb = fb2; s = s2; O = 128; lo = o - 256; }
    else if (o < 448) { fw = fw3; fb = fb3; s = s3; O = 64;  lo = o - 384; }
    else if (o < 512) { fw = fw4; fb = fb4; s = s4; O = 64;  lo = o - 448; }
    else              { fw = fw5; fb = fb5; s = s5; O = 64;  lo = o - 512; }
    const float* st = style + b * 512;
    const float* wp = fw + (size_t)lo * 512;
    float acc = 0.f;
#pragma unroll 4
    for (int i = lane; i < 512; i += 32) acc += st[i] * wp[i];
#pragma unroll
    for (int off = 16; off > 0; off >>= 1)
        acc += __shfl_down_sync(0xffffffffu, acc, off);
    if (lane == 0) s[b * O + lo] = acc + fb[lo];
}

// ---------------------------------------------------------------------------
// Fused weight precombine. Output layout (16 floats per (co,ci)):
//   o[2*(py*4 + aa*2 + bb) + px] = v(py, px, aa, bb)
// i.e. 8 float2 pairs indexed by j = py*4+aa*2+bb, each = (px0, px1).
// ---------------------------------------------------------------------------
__device__ __forceinline__ void combine_one(const float* __restrict__ wp,
                                            float* __restrict__ o) {
    float a[3][3];
#pragma unroll
    for (int ky = 0; ky < 3; ky++)
#pragma unroll
        for (int kx = 0; kx < 3; kx++) a[ky][kx] = wp[ky * 3 + kx];
    float cc[3][2][2];
#pragma unroll
    for (int ky = 0; ky < 3; ky++) {
        cc[ky][0][0] = a[ky][0];
        cc[ky][0][1] = a[ky][1] + a[ky][2];
        cc[ky][1][0] = a[ky][0] + a[ky][1];
        cc[ky][1][1] = a[ky][2];
    }
#pragma unroll
    for (int py = 0; py < 2; py++)
#pragma unroll
        for (int px = 0; px < 2; px++)
#pragma unroll
            for (int aa = 0; aa < 2; aa++)
#pragma unroll
                for (int bb = 0; bb < 2; bb++) {
                    float v;
                    if (py == 0)
                        v = (aa == 0) ? cc[0][px][bb] : cc[1][px][bb] + cc[2][px][bb];
                    else
                        v = (aa == 0) ? cc[0][px][bb] + cc[1][px][bb] : cc[2][px][bb];
                    o[2 * (py * 4 + aa * 2 + bb) + px] = v;
                }
}

#define N1 (256 * 512)
#define N2 (128 * 256)
#define N3 (64 * 128)
#define N4 (64 * 64)
#define N5 (64 * 64)

__global__ void combine_all(const float* __restrict__ w1, float* __restrict__ wc1,
                            const float* __restrict__ w2, float* __restrict__ wc2,
                            const float* __restrict__ w3, float* __restrict__ wc3,
                            const float* __restrict__ w4, float* __restrict__ wc4,
                            const float* __restrict__ w5, float* __restrict__ wc5) {
    int i = blockIdx.x * blockDim.x + threadIdx.x;
    const float* w;
    float* wc;
    int li;
    if (i < N1)                          { w = w1; wc = wc1; li = i; }
    else if (i < N1 + N2)                { w = w2; wc = wc2; li = i - N1; }
    else if (i < N1 + N2 + N3)           { w = w3; wc = wc3; li = i - N1 - N2; }
    else if (i < N1 + N2 + N3 + N4)      { w = w4; wc = wc4; li = i - N1 - N2 - N3; }
    else if (i < N1 + N2 + N3 + N4 + N5) { w = w5; wc = wc5; li = i - N1 - N2 - N3 - N4; }
    else return;
    combine_one(w + (size_t)li * 9, wc + (size_t)li * 16);
}

// ---------------------------------------------------------------------------
// Fused upsample2x + 3x3 conv + style-scale + relu, FFMA2 inner loop.
// acc2[t][ct][py] is a packed float2 = (output px=0, px=1) for row 2m+py.
// ---------------------------------------------------------------------------
template <int CI, int CO, int HS, int WS, int LANES_W, int COT, int YG>
__global__ void __launch_bounds__(32 * YG)
upconv(const float* __restrict__ src, const float* __restrict__ wc,
       const float* __restrict__ sc, float* __restrict__ dst) {
    constexpr int CTH = 2;
    constexpr int RPW = 32 / LANES_W;
    constexpr int MPB = RPW * CTH;                // center rows per block
    constexpr int HO = 2 * HS, WO = 2 * WS;
    constexpr int TR = MPB + 2;                   // tile rows (with halo)
    constexpr int TCP = (LANES_W == 32) ? 34 : (LANES_W == 16 ? 24 : 12);
    constexpr int CHUNK = 8;
    constexpr int NTH = 32 * YG;
    constexpr int TILE = CHUNK * TR * TCP;        // x-tile floats
    constexpr int COB = YG * COT;                 // out channels per block
    constexpr int WTILE = CHUNK * COB * 16;       // weight-tile floats
    constexpr int GROUPS = CO / COB;
    constexpr int NC = CI / CHUNK;

    __shared__ float sbuf[2][TILE];
    __shared__ float wbuf[2][WTILE];

    const int lane = threadIdx.x;
    const int tid = threadIdx.y * 32 + lane;
    const int nl = lane % LANES_W;                // local col (center grid)
    const int ml = (lane / LANES_W) * CTH;        // local center row
    const int col0 = blockIdx.x * LANES_W;
    const int row0 = blockIdx.y * MPB;
    const int n = col0 + nl;
    const int b = blockIdx.z / GROUPS;
    const int cg = blockIdx.z % GROUPS;
    const int co_blk = cg * COB;
    const int co0 = co_blk + threadIdx.y * COT;
    const int m_base = row0 + ml;

    const float* srcb = src + (size_t)b * CI * HS * WS;

    unsigned long long acc2[COT][CTH][2];
#pragma unroll
    for (int t = 0; t < COT; t++)
#pragma unroll
        for (int c = 0; c < CTH; c++)
#pragma unroll
            for (int p = 0; p < 2; p++) acc2[t][c][p] = 0ull;

    // cooperative x-tile loader: tile row 0 = row0-1, tile col 0 = col0-1
    auto load_x = [&](float* buf, int ci0) {
#pragma unroll 2
        for (int idx = tid; idx < TILE; idx += NTH) {
            int cc = idx / (TR * TCP);
            int rem = idx % (TR * TCP);
            int r = rem / TCP, c = rem % TCP;
            int iy = row0 - 1 + r;
            int ix = col0 - 1 + c;
            float v = 0.f;
            if (iy >= 0 && iy < HS && ix >= 0 && ix < WS)
                v = srcb[(size_t)(ci0 + cc) * HS * WS + iy * WS + ix];
            buf[idx] = v;
        }
    };

    // cooperative weight-tile loader (float4 granularity)
    // smem layout: [cc][j][16] with j in [0, COB)
    auto load_w = [&](float* buf, int ci0) {
#pragma unroll 2
        for (int idx = tid; idx < WTILE / 4; idx += NTH) {
            int k4 = idx & 3;
            int rest = idx >> 2;
            int j = rest % COB;
            int cc = rest / COB;
            float4 v = *reinterpret_cast<const float4*>(
                wc + (((size_t)(co_blk + j) * CI + ci0 + cc) << 4) + k4 * 4);
            reinterpret_cast<float4*>(buf)[idx] = v;
        }
    };

    load_x(sbuf[0], 0);
    load_w(wbuf[0], 0);
    __syncthreads();

    for (int k = 0; k < NC; k++) {
        const float* curx = sbuf[k & 1];
        const float* curw = wbuf[k & 1];
        if (k + 1 < NC) {
            load_x(sbuf[(k + 1) & 1], (k + 1) * CHUNK);
            load_w(wbuf[(k + 1) & 1], (k + 1) * CHUNK);
        }
#pragma unroll
        for (int ccI = 0; ccI < CHUNK; ccI++) {
            const float* tp = curx + ccI * TR * TCP;
            // x pairs: x2[r][bb] = (xv[r][bb], xv[r][bb+1])
            unsigned long long x2[CTH + 2][2];
#pragma unroll
            for (int r = 0; r < CTH + 2; r++) {
                float c0 = tp[(ml + r) * TCP + nl + 0];
                float c1 = tp[(ml + r) * TCP + nl + 1];
                float c2 = tp[(ml + r) * TCP + nl + 2];
                x2[r][0] = pack2(c0, c1);
                x2[r][1] = pack2(c1, c2);
            }
#pragma unroll
            for (int t = 0; t < COT; t++) {
                const ulonglong2* wp2 = reinterpret_cast<const ulonglong2*>(
                    curw + (ccI * COB + threadIdx.y * COT + t) * 16);
                ulonglong2 wA = wp2[0], wB = wp2[1], wC = wp2[2], wD = wp2[3];
                unsigned long long w2[8] = {wA.x, wA.y, wB.x, wB.y,
                                            wC.x, wC.y, wD.x, wD.y};
                // w2[py*4 + aa*2 + bb] = (w_px0, w_px1)
#pragma unroll
                for (int ct = 0; ct < CTH; ct++)
#pragma unroll
                    for (int py = 0; py < 2; py++)
#pragma unroll
                        for (int aa = 0; aa < 2; aa++)
#pragma unroll
                            for (int bb = 0; bb < 2; bb++)
                                fma2(acc2[t][ct][py], w2[py * 4 + aa * 2 + bb],
                                     x2[ct + aa + py][bb]);
            }
        }
        __syncthreads();
    }

    // epilogue: scale, relu, float2 store
#pragma unroll
    for (int t = 0; t < COT; t++) {
        const int co = co0 + t;
        const float sv = sc[b * CO + co];
        float* dp = dst + (((size_t)b * CO + co) * HO) * WO;
#pragma unroll
        for (int ct = 0; ct < CTH; ct++) {
            const int m = m_base + ct;
#pragma unroll
            for (int py = 0; py < 2; py++) {
                float v0, v1;
                unpack2(acc2[t][ct][py], v0, v1);
                v0 *= sv; v1 *= sv;
                v0 = v0 > 0.f ? v0 : 0.f;
                v1 = v1 > 0.f ? v1 : 0.f;
                *reinterpret_cast<float2*>(dp + (2 * m + py) * WO + 2 * n) =
                    make_float2(v0, v1);
            }
        }
    }
}

// ---------------------------------------------------------------------------
// Final plain 3x3 conv: 64 -> 3 channels, 256x256, + bias, smem staged.
// ---------------------------------------------------------------------------
__global__ void __launch_bounds__(256)
final_conv(const float* __restrict__ src, const float* __restrict__ wf,
           const float* __restrict__ bf, float* __restrict__ dst) {
    constexpr int H = 256, W = 256, CI = 64;
    constexpr int TCP = 34;
    constexpr int TR = 34;
    constexpr int CHUNK = 2;
    constexpr int TILE = CHUNK * TR * TCP;
    constexpr int NC = CI / CHUNK;

    __shared__ float ws[3 * 64 * 9];
    __shared__ float xs[2][TILE];

    const int tid = threadIdx.x;
    for (int i = tid; i < 3 * 64 * 9; i += 256) ws[i] = wf[i];

    const int b = blockIdx.z;
    const int tx = tid % 16, ty = tid / 16;
    const int col0 = blockIdx.x * 32;
    const int row0 = blockIdx.y * 32;
    const int px0 = col0 + tx * 2;
    const int py0 = row0 + ty * 2;

    const float* srcb = src + (size_t)b * CI * H * W;

    auto load_chunk = [&](float* buf, int ci0) {
#pragma unroll 2
        for (int idx = tid; idx < TILE; idx += 256) {
            int cc = idx / (TR * TCP);
            int rem = idx % (TR * TCP);
            int r = rem / TCP, c = rem % TCP;
            int iy = row0 - 1 + r;
            int ix = col0 - 1 + c;
            float v = 0.f;
            if (iy >= 0 && iy < H && ix >= 0 && ix < W)
                v = srcb[(size_t)(ci0 + cc) * H * W + iy * W + ix];
            buf[idx] = v;
        }
    };

    // packed accumulators: acc2[co][dy] = (dx0, dx1)
    unsigned long long acc2[3][2];
#pragma unroll
    for (int c = 0; c < 3; c++)
#pragma unroll
        for (int p = 0; p < 2; p++) acc2[c][p] = 0ull;

    load_chunk(xs[0], 0);
    __syncthreads();

    for (int k = 0; k < NC; k++) {
        const float* cur = xs[k & 1];
        if (k + 1 < NC) load_chunk(xs[(k + 1) & 1], (k + 1) * CHUNK);
        const int ci0 = k * CHUNK;
#pragma unroll
        for (int ccI = 0; ccI < CHUNK; ccI++) {
            const float* tp = cur + ccI * TR * TCP;
            // x pairs per row: x2[r][kx] = (xv[r][kx], xv[r][kx+1]), kx=0..2
            unsigned long long x2[4][3];
#pragma unroll
            for (int r = 0; r < 4; r++) {
                float c0 = tp[(ty * 2 + r) * TCP + tx * 2 + 0];
                float c1 = tp[(ty * 2 + r) * TCP + tx * 2 + 1];
                float c2 = tp[(ty * 2 + r) * TCP + tx * 2 + 2];
                float c3 = tp[(ty * 2 + r) * TCP + tx * 2 + 3];
                x2[r][0] = pack2(c0, c1);
                x2[r][1] = pack2(c1, c2);
                x2[r][2] = pack2(c2, c3);
            }
            const int ci = ci0 + ccI;
#pragma unroll
            for (int co = 0; co < 3; co++) {
                const float* wsp = ws + co * (64 * 9) + ci * 9;
#pragma unroll
                for (int ky = 0; ky < 3; ky++)
#pragma unroll
                    for (int kx = 0; kx < 3; kx++) {
                        float w = wsp[ky * 3 + kx];
                        unsigned long long w2 = pack2(w, w);
#pragma unroll
                        for (int dy = 0; dy < 2; dy++)
                            fma2(acc2[co][dy], w2, x2[dy + ky][kx]);
                    }
            }
        }
        __syncthreads();
    }

#pragma unroll
    for (int co = 0; co < 3; co++) {
        float bias = bf[co];
        float* dp = dst + (((size_t)b * 3 + co) * H) * W;
#pragma unroll
        for (int dy = 0; dy < 2; dy++) {
            float v0, v1;
            unpack2(acc2[co][dy], v0, v1);
            *reinterpret_cast<float2*>(dp + (py0 + dy) * W + px0) =
                make_float2(v0 + bias, v1 + bias);
        }
    }
}

// ---------------------------------------------------------------------------
// launch
// ---------------------------------------------------------------------------
static void* sym(const void* s) {
    void* p = nullptr;
    cudaGetSymbolAddress(&p, s);
    return p;
}

extern "C" void kernel_launch(void* const* d_in, const int* in_sizes, int n_in,
                              void* d_out, int out_size) {
    const float* x     = (const float*)d_in[0];
    const float* style = (const float*)d_in[1];
    const float* w1 = (const float*)d_in[2];
    const float* fw1 = (const float*)d_in[3];
    const float* fb1 = (const float*)d_in[4];
    const float* w2 = (const float*)d_in[5];
    const float* fw2 = (const float*)d_in[6];
    const float* fb2 = (const float*)d_in[7];
    const float* w3 = (const float*)d_in[8];
    const float* fw3 = (const float*)d_in[9];
    const float* fb3 = (const float*)d_in[10];
    const float* w4 = (const float*)d_in[11];
    const float* fw4 = (const float*)d_in[12];
    const float* fb4 = (const float*)d_in[13];
    const float* w5 = (const float*)d_in[14];
    const float* fw5 = (const float*)d_in[15];
    const float* fb5 = (const float*)d_in[16];
    const float* wf = (const float*)d_in[17];
    const float* bf = (const float*)d_in[18];

    float* a1 = (float*)sym(g_a1);
    float* a2 = (float*)sym(g_a2);
    float* a3 = (float*)sym(g_a3);
    float* a4 = (float*)sym(g_a4);
    float* a5 = (float*)sym(g_a5);
    float* wc1 = (float*)sym(g_wc1);
    float* wc2 = (float*)sym(g_wc2);
    float* wc3 = (float*)sym(g_wc3);
    float* wc4 = (float*)sym(g_wc4);
    float* wc5 = (float*)sym(g_wc5);
    float* s1 = (float*)sym(g_s1);
    float* s2 = (float*)sym(g_s2);
    float* s3 = (float*)sym(g_s3);
    float* s4 = (float*)sym(g_s4);
    float* s5 = (float*)sym(g_s5);

    // fused prologue
    {
        int ntot = N1 + N2 + N3 + N4 + N5;
        combine_all<<<(ntot + 255) / 256, 256>>>(w1, wc1, w2, wc2, w3, wc3,
                                                 w4, wc4, w5, wc5);
        int warps = B_ * 576;
        style_all<<<(warps * 32 + 255) / 256, 256>>>(style,
                                                     fw1, fb1, s1, fw2, fb2, s2,
                                                     fw3, fb3, s3, fw4, fb4, s4,
                                                     fw5, fb5, s5);
    }

    // L1: 512->256, 8x8 -> 16x16.  256 thr, COT=2, YG=8 (16 co/block, 128 blocks)
    upconv<512, 256, 8, 8, 8, 2, 8><<<dim3(1, 1, B_ * 16), dim3(32, 8)>>>(x, wc1, s1, a1);
    // L2: 256->128, 16 -> 32.  256 thr, COT=2, YG=8 (16 co/block, 256 blocks)
    upconv<256, 128, 16, 16, 16, 2, 8><<<dim3(1, 4, B_ * 8), dim3(32, 8)>>>(a1, wc2, s2, a2);
    // L3: 128->64, 32 -> 64.  128 thr, COT=4, YG=4 (512 blocks)
    upconv<128, 64, 32, 32, 32, 4, 4><<<dim3(1, 16, B_ * 4), dim3(32, 4)>>>(a2, wc3, s3, a3);
    // L4: 64->64, 64 -> 128  (2048 blocks)
    upconv<64, 64, 64, 64, 32, 4, 4><<<dim3(2, 32, B_ * 4), dim3(32, 4)>>>(a3, wc4, s4, a4);
    // L5: 64->64, 128 -> 256  (8192 blocks)
    upconv<64, 64, 128, 128, 32, 4, 4><<<dim3(4, 64, B_ * 4), dim3(32, 4)>>>(a4, wc5, s5, a5);

    // final conv 64 -> 3 + bias
    final_conv<<<dim3(8, 8, B_), 256>>>(a5, wf, bf, (float*)d_out);
}

// round 10
// speedup vs baseline: 1.9078x; 1.1256x over previous
#include <cuda_runtime.h>
#include <cuda_bf16.h>
#include <cstdint>

// ---------------------------------------------------------------------------
// Decoder: x[8,512,8,8], style[8,512]
//  5 x { upsample2x -> modconv3x3 -> relu }  then final conv3x3 + bias
// upsample2x + conv3x3(pad1) == per-parity 2x2 conv on the SOURCE grid.
// v6: L4/L5 (64->64ch) on mma.sync m16n8k16 bf16 (HMMA, baseline sm_103
// feature) with 3-product hi/lo split precision:
//   D = xh*wh + xh*wl + xl*wh   (xl*wl ~2^-18 relative, dropped)
// L1-L3 + final conv stay on the tuned scalar FFMA2 path.
// ---------------------------------------------------------------------------

#define B_ 8

// ---- static scratch (no allocations allowed) ----
__device__ float g_a1[B_ * 256 * 16 * 16];
__device__ float g_a2[B_ * 128 * 32 * 32];
__device__ float g_a3[B_ * 64 * 64 * 64];
__device__ float g_a4[B_ * 64 * 128 * 128];
__device__ float g_a5[B_ * 64 * 256 * 256];

__device__ float g_wc1[256 * 512 * 16];
__device__ float g_wc2[128 * 256 * 16];
__device__ float g_wc3[64 * 128 * 16];

// L4/L5 MMA weights: per parity p, [co][k] bf16, k = ci*4 + aa*2 + bb (K=256)
// hi and lo split parts, row-major (padded only in smem).
__device__ unsigned short g_wH4[4 * 64 * 256];
__device__ unsigned short g_wL4[4 * 64 * 256];
__device__ unsigned short g_wH5[4 * 64 * 256];
__device__ unsigned short g_wL5[4 * 64 * 256];

__device__ float g_s1[B_ * 256];
__device__ float g_s2[B_ * 128];
__device__ float g_s3[B_ * 64];
__device__ float g_s4[B_ * 64];
__device__ float g_s5[B_ * 64];

// ---- packed f32x2 helpers (scalar path) ----
__device__ __forceinline__ unsigned long long pack2(float lo, float hi) {
    unsigned long long r;
    asm("mov.b64 %0, {%1, %2};" : "=l"(r) : "f"(lo), "f"(hi));
    return r;
}
__device__ __forceinline__ void unpack2(unsigned long long v, float& lo, float& hi) {
    asm("mov.b64 {%0, %1}, %2;" : "=f"(lo), "=f"(hi) : "l"(v));
}
__device__ __forceinline__ void fma2(unsigned long long& d, unsigned long long a,
                                     unsigned long long b) {
    asm("fma.rn.f32x2 %0, %1, %2, %0;" : "+l"(d) : "l"(a), "l"(b));
}

__device__ __forceinline__ uint32_t smem_u32(const void* p) {
    uint32_t a;
    asm("{ .reg .u64 t; cvta.to.shared.u64 t, %1; cvt.u32.u64 %0, t; }"
        : "=r"(a) : "l"(p));
    return a;
}

// bf16 hi/lo split
__device__ __forceinline__ void split_bf(float v, unsigned short& h, unsigned short& l) {
    __nv_bfloat16 hb = __float2bfloat16(v);
    float hf = __bfloat162float(hb);
    __nv_bfloat16 lb = __float2bfloat16(v - hf);
    h = __bfloat16_as_ushort(hb);
    l = __bfloat16_as_ushort(lb);
}

// ---- mma / ldmatrix wrappers (baseline sm_80+ features) ----
#define LDSM_X4(r0, r1, r2, r3, addr)                                          \
    asm volatile("ldmatrix.sync.aligned.m8n8.x4.shared.b16 {%0,%1,%2,%3}, [%4];" \
                 : "=r"(r0), "=r"(r1), "=r"(r2), "=r"(r3) : "r"(addr))

__device__ __forceinline__ void mma_bf16(float* d, uint32_t a0, uint32_t a1,
                                         uint32_t a2, uint32_t a3,
                                         uint32_t b0, uint32_t b1) {
    asm volatile(
        "mma.sync.aligned.m16n8k16.row.col.f32.bf16.bf16.f32 "
        "{%0,%1,%2,%3},{%4,%5,%6,%7},{%8,%9},{%0,%1,%2,%3};"
        : "+f"(d[0]), "+f"(d[1]), "+f"(d[2]), "+f"(d[3])
        : "r"(a0), "r"(a1), "r"(a2), "r"(a3), "r"(b0), "r"(b1));
}

// ---------------------------------------------------------------------------
// Fused style FC for all 5 layers: one warp per (b, concat-output)
// ---------------------------------------------------------------------------
__global__ void style_all(const float* __restrict__ style,
                          const float* __restrict__ fw1, const float* __restrict__ fb1, float* __restrict__ s1,
                          const float* __restrict__ fw2, const float* __restrict__ fb2, float* __restrict__ s2,
                          const float* __restrict__ fw3, const float* __restrict__ fb3, float* __restrict__ s3,
                          const float* __restrict__ fw4, const float* __restrict__ fb4, float* __restrict__ s4,
                          const float* __restrict__ fw5, const float* __restrict__ fb5, float* __restrict__ s5) {
    int warp = (blockIdx.x * blockDim.x + threadIdx.x) >> 5;
    int lane = threadIdx.x & 31;
    if (warp >= B_ * 576) return;
    int b = warp / 576;
    int o = warp % 576;
    const float *fw, *fb;
    float* s;
    int O, lo;
    if (o < 256)      { fw = fw1; fb = fb1; s = s1; O = 256; lo = o; }
    else if (o < 384) { fw = fw2; fb = fb2; s = s2; O = 128; lo = o - 256; }
    else if (o < 448) { fw = fw3; fb = fb3; s = s3; O = 64;  lo = o - 384; }
    else if (o < 512) { fw = fw4; fb = fb4; s = s4; O = 64;  lo = o - 448; }
    else              { fw = fw5; fb = fb5; s = s5; O = 64;  lo = o - 512; }
    const float* st = style + b * 512;
    const float* wp = fw + (size_t)lo * 512;
    float acc = 0.f;
#pragma unroll 4
    for (int i = lane; i < 512; i += 32) acc += st[i] * wp[i];
#pragma unroll
    for (int off = 16; off > 0; off >>= 1)
        acc += __shfl_down_sync(0xffffffffu, acc, off);
    if (lane == 0) s[b * O + lo] = acc + fb[lo];
}

// ---------------------------------------------------------------------------
// Combined parity weight math: v(py,px,aa,bb) from 3x3 kernel a[ky][kx]
// ---------------------------------------------------------------------------
__device__ __forceinline__ void combine_vals(const float a[3][3], float out[2][2][2][2]) {
    float cc[3][2][2];
#pragma unroll
    for (int ky = 0; ky < 3; ky++) {
        cc[ky][0][0] = a[ky][0];
        cc[ky][0][1] = a[ky][1] + a[ky][2];
        cc[ky][1][0] = a[ky][0] + a[ky][1];
        cc[ky][1][1] = a[ky][2];
    }
#pragma unroll
    for (int py = 0; py < 2; py++)
#pragma unroll
        for (int px = 0; px < 2; px++)
#pragma unroll
            for (int aa = 0; aa < 2; aa++)
#pragma unroll
                for (int bb = 0; bb < 2; bb++) {
                    float v;
                    if (py == 0)
                        v = (aa == 0) ? cc[0][px][bb] : cc[1][px][bb] + cc[2][px][bb];
                    else
                        v = (aa == 0) ? cc[0][px][bb] + cc[1][px][bb] : cc[2][px][bb];
                    out[py][px][aa][bb] = v;
                }
}

// scalar-path precombine: o[2*(py*4+aa*2+bb)+px] (px-interleaved pairs)
__device__ __forceinline__ void combine_one(const float* __restrict__ wp,
                                            float* __restrict__ o) {
    float a[3][3];
#pragma unroll
    for (int ky = 0; ky < 3; ky++)
#pragma unroll
        for (int kx = 0; kx < 3; kx++) a[ky][kx] = wp[ky * 3 + kx];
    float v[2][2][2][2];
    combine_vals(a, v);
#pragma unroll
    for (int py = 0; py < 2; py++)
#pragma unroll
        for (int px = 0; px < 2; px++)
#pragma unroll
            for (int aa = 0; aa < 2; aa++)
#pragma unroll
                for (int bb = 0; bb < 2; bb++)
                    o[2 * (py * 4 + aa * 2 + bb) + px] = v[py][px][aa][bb];
}

#define N1 (256 * 512)
#define N2 (128 * 256)
#define N3 (64 * 128)

__global__ void combine_all(const float* __restrict__ w1, float* __restrict__ wc1,
                            const float* __restrict__ w2, float* __restrict__ wc2,
                            const float* __restrict__ w3, float* __restrict__ wc3) {
    int i = blockIdx.x * blockDim.x + threadIdx.x;
    const float* w;
    float* wc;
    int li;
    if (i < N1)                { w = w1; wc = wc1; li = i; }
    else if (i < N1 + N2)      { w = w2; wc = wc2; li = i - N1; }
    else if (i < N1 + N2 + N3) { w = w3; wc = wc3; li = i - N1 - N2; }
    else return;
    combine_one(w + (size_t)li * 9, wc + (size_t)li * 16);
}

// ---------------------------------------------------------------------------
// Build L4/L5 MMA weights: per parity, [co][k] bf16 hi/lo, k = ci*4+aa*2+bb.
// ---------------------------------------------------------------------------
__global__ void build_wHL(const float* __restrict__ w4, const float* __restrict__ w5,
                          unsigned short* __restrict__ h4, unsigned short* __restrict__ l4,
                          unsigned short* __restrict__ h5, unsigned short* __restrict__ l5) {
    int i = blockIdx.x * blockDim.x + threadIdx.x;
    if (i >= 2 * 4096) return;
    const float* w = (i < 4096) ? w4 : w5;
    unsigned short* hh = (i < 4096) ? h4 : h5;
    unsigned short* ll = (i < 4096) ? l4 : l5;
    int li = i & 4095;
    int co = li >> 6, ci = li & 63;
    const float* wp = w + (size_t)li * 9;
    float a[3][3];
#pragma unroll
    for (int ky = 0; ky < 3; ky++)
#pragma unroll
        for (int kx = 0; kx < 3; kx++) a[ky][kx] = wp[ky * 3 + kx];
    float v[2][2][2][2];
    combine_vals(a, v);
#pragma unroll
    for (int py = 0; py < 2; py++)
#pragma unroll
        for (int px = 0; px < 2; px++) {
            int p = py * 2 + px;
#pragma unroll
            for (int aa = 0; aa < 2; aa++)
#pragma unroll
                for (int bb = 0; bb < 2; bb++) {
                    unsigned short h, l;
                    split_bf(v[py][px][aa][bb], h, l);
                    int k = ci * 4 + aa * 2 + bb;
                    hh[p * 16384 + co * 256 + k] = h;
                    ll[p * 16384 + co * 256 + k] = l;
                }
        }
}

// ---------------------------------------------------------------------------
// HMMA upconv for CI=CO=64 layers (L4, L5).
// Grid: (WS/8, HS/8, B*4). CTA = 8x8 source centers (64), one parity.
// GEMM: M=64 centers, N=64 co, K=256.  8 warps, each 16 centers x 32 co.
// smem: xh/xl [64][264] bf16 (im2col, split), wh/wl [64][264] bf16.
// Padded stride 264 -> 528B row = conflict-free ldmatrix.
// ---------------------------------------------------------------------------
template <int HS, int WS>
__global__ void __launch_bounds__(256)
upconv_mma(const float* __restrict__ src,
           const unsigned short* __restrict__ wH, const unsigned short* __restrict__ wL,
           const float* __restrict__ sc, float* __restrict__ dst) {
    constexpr int CO = 64;
    constexpr int HO = 2 * HS, WO = 2 * WS;
    constexpr int SP = 264;                 // padded k-stride (elements)
    constexpr int ROW_U4 = SP / 8;          // 33 uint4 per row

    extern __shared__ unsigned short smem[];
    unsigned short* xh = smem;
    unsigned short* xl = xh + 64 * SP;
    unsigned short* wh = xl + 64 * SP;
    unsigned short* wl = wh + 64 * SP;
    __shared__ float ssc[64];

    const int tid = threadIdx.x;
    const int wid = tid >> 5, lane = tid & 31;

    const int p = blockIdx.z & 3, b = blockIdx.z >> 2;
    const int py = p >> 1, px = p & 1;
    const int m0 = blockIdx.y * 8, n0 = blockIdx.x * 8;

    // ---- load weights (hi/lo) into padded smem rows ----
    {
        const uint4* gh = (const uint4*)(wH + p * 16384);
        const uint4* gl = (const uint4*)(wL + p * 16384);
        uint4* sh = (uint4*)wh;
        uint4* sl = (uint4*)wl;
#pragma unroll 4
        for (int i = tid; i < 2048; i += 256) {
            int co = i >> 5, j = i & 31;
            sh[co * ROW_U4 + j] = gh[i];
            sl[co * ROW_U4 + j] = gl[i];
        }
    }
    if (tid < 64) ssc[tid] = sc[b * 64 + tid];

    // ---- im2col + split: xh/xl[n][ci*4 + aa*2 + bb] ----
    {
        const float* sp_b = src + (size_t)b * 64 * HS * WS;
#pragma unroll 4
        for (int q = tid; q < 4096; q += 256) {
            int n = q & 63, ci = q >> 6;
            int mr = n >> 3, nc = n & 7;
            int iy0 = m0 + mr - 1 + py;
            int ix0 = n0 + nc - 1 + px;
            const float* sp = sp_b + (size_t)ci * HS * WS;
            bool y0 = (iy0 >= 0) && (iy0 < HS);
            bool y1 = (iy0 + 1 < HS);
            bool x0 = (ix0 >= 0) && (ix0 < WS);
            bool x1 = (ix0 + 1 < WS);
            float v00 = (y0 && x0) ? sp[iy0 * WS + ix0] : 0.f;
            float v01 = (y0 && x1) ? sp[iy0 * WS + ix0 + 1] : 0.f;
            float v10 = (y1 && x0) ? sp[(iy0 + 1) * WS + ix0] : 0.f;
            float v11 = (y1 && x1) ? sp[(iy0 + 1) * WS + ix0 + 1] : 0.f;
            unsigned short h00, l00, h01, l01, h10, l10, h11, l11;
            split_bf(v00, h00, l00);
            split_bf(v01, h01, l01);
            split_bf(v10, h10, l10);
            split_bf(v11, h11, l11);
            int e = n * SP + ci * 4;
            *(uint2*)(xh + e) = make_uint2((uint32_t)h00 | ((uint32_t)h01 << 16),
                                           (uint32_t)h10 | ((uint32_t)h11 << 16));
            *(uint2*)(xl + e) = make_uint2((uint32_t)l00 | ((uint32_t)l01 << 16),
                                           (uint32_t)l10 | ((uint32_t)l11 << 16));
        }
    }
    __syncthreads();

    // ---- warp tiles: mt = wid>>1 (centers 16mt..), ch2 = wid&1 (co 32*ch2..) ----
    const int mt = wid >> 1;
    const int ch2 = wid & 1;

    float d[4][4];
#pragma unroll
    for (int nt = 0; nt < 4; nt++)
#pragma unroll
        for (int j = 0; j < 4; j++) d[nt][j] = 0.f;

    // ldmatrix per-thread row addresses
    const int g = lane >> 3, gi = lane & 7;
    // A: groups: (g&1) -> row block, (g>>1) -> k block
    const int arow = mt * 16 + (g & 1) * 8 + gi;
    const int acol = (g >> 1) * 8;
    uint32_t aAddrH = smem_u32(xh + arow * SP + acol);
    uint32_t aAddrL = smem_u32(xl + arow * SP + acol);
    // B pair q: rows co = ch2*32 + q*16 + (g>>1)*8 + gi, col (g&1)*8
    const int bcol = (g & 1) * 8;
    const int brow0 = ch2 * 32 + 0 * 16 + (g >> 1) * 8 + gi;
    const int brow1 = ch2 * 32 + 1 * 16 + (g >> 1) * 8 + gi;
    uint32_t bAddrH0 = smem_u32(wh + brow0 * SP + bcol);
    uint32_t bAddrH1 = smem_u32(wh + brow1 * SP + bcol);
    uint32_t bAddrL0 = smem_u32(wl + brow0 * SP + bcol);
    uint32_t bAddrL1 = smem_u32(wl + brow1 * SP + bcol);

#pragma unroll
    for (int ks = 0; ks < 16; ks++) {
        const uint32_t koff = ks * 32;  // 16 bf16 = 32 bytes
        uint32_t ah0, ah1, ah2, ah3, al0, al1, al2, al3;
        LDSM_X4(ah0, ah1, ah2, ah3, aAddrH + koff);
        LDSM_X4(al0, al1, al2, al3, aAddrL + koff);
        uint32_t bh[2][4], bl[2][4];
        LDSM_X4(bh[0][0], bh[0][1], bh[0][2], bh[0][3], bAddrH0 + koff);
        LDSM_X4(bh[1][0], bh[1][1], bh[1][2], bh[1][3], bAddrH1 + koff);
        LDSM_X4(bl[0][0], bl[0][1], bl[0][2], bl[0][3], bAddrL0 + koff);
        LDSM_X4(bl[1][0], bl[1][1], bl[1][2], bl[1][3], bAddrL1 + koff);
#pragma unroll
        for (int nt = 0; nt < 4; nt++) {
            const int q = nt >> 1, lc = nt & 1;
            uint32_t b0h = bh[q][lc * 2], b1h = bh[q][lc * 2 + 1];
            uint32_t b0l = bl[q][lc * 2], b1l = bl[q][lc * 2 + 1];
            mma_bf16(d[nt], ah0, ah1, ah2, ah3, b0h, b1h);  // xh*wh
            mma_bf16(d[nt], ah0, ah1, ah2, ah3, b0l, b1l);  // xh*wl
            mma_bf16(d[nt], al0, al1, al2, al3, b0h, b1h);  // xl*wh
        }
    }

    // ---- epilogue: scale, relu, store ----
    const int r = lane >> 2;
    const int cp = (lane & 3) * 2;
#pragma unroll
    for (int nt = 0; nt < 4; nt++) {
        const int co0 = ch2 * 32 + nt * 8 + cp;
#pragma unroll
        for (int half = 0; half < 2; half++) {
            const int m = mt * 16 + r + half * 8;
            const int mr = m >> 3, nc = m & 7;
            const int oy = 2 * (m0 + mr) + py;
            const int ox = 2 * (n0 + nc) + px;
#pragma unroll
            for (int j = 0; j < 2; j++) {
                const int co = co0 + j;
                float v = d[nt][half * 2 + j] * ssc[co];
                v = v > 0.f ? v : 0.f;
                dst[((size_t)(b * CO + co) * HO + oy) * WO + ox] = v;
            }
        }
    }
}

// ---------------------------------------------------------------------------
// Scalar upconv (L1-L3), FFMA2 inner loop (unchanged).
// ---------------------------------------------------------------------------
template <int CI, int CO, int HS, int WS, int LANES_W, int COT, int YG>
__global__ void __launch_bounds__(32 * YG)
upconv(const float* __restrict__ src, const float* __restrict__ wc,
       const float* __restrict__ sc, float* __restrict__ dst) {
    constexpr int CTH = 2;
    constexpr int RPW = 32 / LANES_W;
    constexpr int MPB = RPW * CTH;
    constexpr int HO = 2 * HS, WO = 2 * WS;
    constexpr int TR = MPB + 2;
    constexpr int TCP = (LANES_W == 32) ? 34 : (LANES_W == 16 ? 24 : 12);
    constexpr int CHUNK = 8;
    constexpr int NTH = 32 * YG;
    constexpr int TILE = CHUNK * TR * TCP;
    constexpr int COB = YG * COT;
    constexpr int WTILE = CHUNK * COB * 16;
    constexpr int GROUPS = CO / COB;
    constexpr int NC = CI / CHUNK;

    __shared__ float sbuf[2][TILE];
    __shared__ float wbuf[2][WTILE];

    const int lane = threadIdx.x;
    const int tid = threadIdx.y * 32 + lane;
    const int nl = lane % LANES_W;
    const int ml = (lane / LANES_W) * CTH;
    const int col0 = blockIdx.x * LANES_W;
    const int row0 = blockIdx.y * MPB;
    const int n = col0 + nl;
    const int b = blockIdx.z / GROUPS;
    const int cg = blockIdx.z % GROUPS;
    const int co_blk = cg * COB;
    const int co0 = co_blk + threadIdx.y * COT;
    const int m_base = row0 + ml;

    const float* srcb = src + (size_t)b * CI * HS * WS;

    unsigned long long acc2[COT][CTH][2];
#pragma unroll
    for (int t = 0; t < COT; t++)
#pragma unroll
        for (int c = 0; c < CTH; c++)
#pragma unroll
            for (int p = 0; p < 2; p++) acc2[t][c][p] = 0ull;

    auto load_x = [&](float* buf, int ci0) {
#pragma unroll 2
        for (int idx = tid; idx < TILE; idx += NTH) {
            int cc = idx / (TR * TCP);
            int rem = idx % (TR * TCP);
            int r = rem / TCP, c = rem % TCP;
            int iy = row0 - 1 + r;
            int ix = col0 - 1 + c;
            float v = 0.f;
            if (iy >= 0 && iy < HS && ix >= 0 && ix < WS)
                v = srcb[(size_t)(ci0 + cc) * HS * WS + iy * WS + ix];
            buf[idx] = v;
        }
    };
    auto load_w = [&](float* buf, int ci0) {
#pragma unroll 2
        for (int idx = tid; idx < WTILE / 4; idx += NTH) {
            int k4 = idx & 3;
            int rest = idx >> 2;
            int j = rest % COB;
            int cc = rest / COB;
            float4 v = *reinterpret_cast<const float4*>(
                wc + (((size_t)(co_blk + j) * CI + ci0 + cc) << 4) + k4 * 4);
            reinterpret_cast<float4*>(buf)[idx] = v;
        }
    };

    load_x(sbuf[0], 0);
    load_w(wbuf[0], 0);
    __syncthreads();

    for (int k = 0; k < NC; k++) {
        const float* curx = sbuf[k & 1];
        const float* curw = wbuf[k & 1];
        if (k + 1 < NC) {
            load_x(sbuf[(k + 1) & 1], (k + 1) * CHUNK);
            load_w(wbuf[(k + 1) & 1], (k + 1) * CHUNK);
        }
#pragma unroll
        for (int ccI = 0; ccI < CHUNK; ccI++) {
            const float* tp = curx + ccI * TR * TCP;
            unsigned long long x2[CTH + 2][2];
#pragma unroll
            for (int r = 0; r < CTH + 2; r++) {
                float c0 = tp[(ml + r) * TCP + nl + 0];
                float c1 = tp[(ml + r) * TCP + nl + 1];
                float c2 = tp[(ml + r) * TCP + nl + 2];
                x2[r][0] = pack2(c0, c1);
                x2[r][1] = pack2(c1, c2);
            }
#pragma unroll
            for (int t = 0; t < COT; t++) {
                const ulonglong2* wp2 = reinterpret_cast<const ulonglong2*>(
                    curw + (ccI * COB + threadIdx.y * COT + t) * 16);
                ulonglong2 wA_ = wp2[0], wB_ = wp2[1], wC_ = wp2[2], wD_ = wp2[3];
                unsigned long long w2[8] = {wA_.x, wA_.y, wB_.x, wB_.y,
                                            wC_.x, wC_.y, wD_.x, wD_.y};
#pragma unroll
                for (int ct = 0; ct < CTH; ct++)
#pragma unroll
                    for (int py = 0; py < 2; py++)
#pragma unroll
                        for (int aa = 0; aa < 2; aa++)
#pragma unroll
                            for (int bb = 0; bb < 2; bb++)
                                fma2(acc2[t][ct][py], w2[py * 4 + aa * 2 + bb],
                                     x2[ct + aa + py][bb]);
            }
        }
        __syncthreads();
    }

#pragma unroll
    for (int t = 0; t < COT; t++) {
        const int co = co0 + t;
        const float sv = sc[b * CO + co];
        float* dp = dst + (((size_t)b * CO + co) * HO) * WO;
#pragma unroll
        for (int ct = 0; ct < CTH; ct++) {
            const int m = m_base + ct;
#pragma unroll
            for (int py = 0; py < 2; py++) {
                float v0, v1;
                unpack2(acc2[t][ct][py], v0, v1);
                v0 *= sv; v1 *= sv;
                v0 = v0 > 0.f ? v0 : 0.f;
                v1 = v1 > 0.f ? v1 : 0.f;
                *reinterpret_cast<float2*>(dp + (2 * m + py) * WO + 2 * n) =
                    make_float2(v0, v1);
            }
        }
    }
}

// ---------------------------------------------------------------------------
// Final plain 3x3 conv: 64 -> 3 channels, 256x256, + bias, smem staged.
// ---------------------------------------------------------------------------
__global__ void __launch_bounds__(256)
final_conv(const float* __restrict__ src, const float* __restrict__ wf,
           const float* __restrict__ bf, float* __restrict__ dst) {
    constexpr int H = 256, W = 256, CI = 64;
    constexpr int TCP = 34;
    constexpr int TR = 34;
    constexpr int CHUNK = 2;
    constexpr int TILE = CHUNK * TR * TCP;
    constexpr int NC = CI / CHUNK;

    __shared__ float ws[3 * 64 * 9];
    __shared__ float xs[2][TILE];

    const int tid = threadIdx.x;
    for (int i = tid; i < 3 * 64 * 9; i += 256) ws[i] = wf[i];

    const int b = blockIdx.z;
    const int tx = tid % 16, ty = tid / 16;
    const int col0 = blockIdx.x * 32;
    const int row0 = blockIdx.y * 32;
    const int px0 = col0 + tx * 2;
    const int py0 = row0 + ty * 2;

    const float* srcb = src + (size_t)b * CI * H * W;

    auto load_chunk = [&](float* buf, int ci0) {
#pragma unroll 2
        for (int idx = tid; idx < TILE; idx += 256) {
            int cc = idx / (TR * TCP);
            int rem = idx % (TR * TCP);
            int r = rem / TCP, c = rem % TCP;
            int iy = row0 - 1 + r;
            int ix = col0 - 1 + c;
            float v = 0.f;
            if (iy >= 0 && iy < H && ix >= 0 && ix < W)
                v = srcb[(size_t)(ci0 + cc) * H * W + iy * W + ix];
            buf[idx] = v;
        }
    };

    unsigned long long acc2[3][2];
#pragma unroll
    for (int c = 0; c < 3; c++)
#pragma unroll
        for (int p = 0; p < 2; p++) acc2[c][p] = 0ull;

    load_chunk(xs[0], 0);
    __syncthreads();

    for (int k = 0; k < NC; k++) {
        const float* cur = xs[k & 1];
        if (k + 1 < NC) load_chunk(xs[(k + 1) & 1], (k + 1) * CHUNK);
        const int ci0 = k * CHUNK;
#pragma unroll
        for (int ccI = 0; ccI < CHUNK; ccI++) {
            const float* tp = cur + ccI * TR * TCP;
            unsigned long long x2[4][3];
#pragma unroll
            for (int r = 0; r < 4; r++) {
                float c0 = tp[(ty * 2 + r) * TCP + tx * 2 + 0];
                float c1 = tp[(ty * 2 + r) * TCP + tx * 2 + 1];
                float c2 = tp[(ty * 2 + r) * TCP + tx * 2 + 2];
                float c3 = tp[(ty * 2 + r) * TCP + tx * 2 + 3];
                x2[r][0] = pack2(c0, c1);
                x2[r][1] = pack2(c1, c2);
                x2[r][2] = pack2(c2, c3);
            }
            const int ci = ci0 + ccI;
#pragma unroll
            for (int co = 0; co < 3; co++) {
                const float* wsp = ws + co * (64 * 9) + ci * 9;
#pragma unroll
                for (int ky = 0; ky < 3; ky++)
#pragma unroll
                    for (int kx = 0; kx < 3; kx++) {
                        float w = wsp[ky * 3 + kx];
                        unsigned long long w2 = pack2(w, w);
#pragma unroll
                        for (int dy = 0; dy < 2; dy++)
                            fma2(acc2[co][dy], w2, x2[dy + ky][kx]);
                    }
            }
        }
        __syncthreads();
    }

#pragma unroll
    for (int co = 0; co < 3; co++) {
        float bias = bf[co];
        float* dp = dst + (((size_t)b * 3 + co) * H) * W;
#pragma unroll
        for (int dy = 0; dy < 2; dy++) {
            float v0, v1;
            unpack2(acc2[co][dy], v0, v1);
            *reinterpret_cast<float2*>(dp + (py0 + dy) * W + px0) =
                make_float2(v0 + bias, v1 + bias);
        }
    }
}

// ---------------------------------------------------------------------------
// launch
// ---------------------------------------------------------------------------
static void* sym(const void* s) {
    void* p = nullptr;
    cudaGetSymbolAddress(&p, s);
    return p;
}

extern "C" void kernel_launch(void* const* d_in, const int* in_sizes, int n_in,
                              void* d_out, int out_size) {
    const float* x     = (const float*)d_in[0];
    const float* style = (const float*)d_in[1];
    const float* w1 = (const float*)d_in[2];
    const float* fw1 = (const float*)d_in[3];
    const float* fb1 = (const float*)d_in[4];
    const float* w2 = (const float*)d_in[5];
    const float* fw2 = (const float*)d_in[6];
    const float* fb2 = (const float*)d_in[7];
    const float* w3 = (const float*)d_in[8];
    const float* fw3 = (const float*)d_in[9];
    const float* fb3 = (const float*)d_in[10];
    const float* w4 = (const float*)d_in[11];
    const float* fw4 = (const float*)d_in[12];
    const float* fb4 = (const float*)d_in[13];
    const float* w5 = (const float*)d_in[14];
    const float* fw5 = (const float*)d_in[15];
    const float* fb5 = (const float*)d_in[16];
    const float* wf = (const float*)d_in[17];
    const float* bf = (const float*)d_in[18];

    float* a1 = (float*)sym(g_a1);
    float* a2 = (float*)sym(g_a2);
    float* a3 = (float*)sym(g_a3);
    float* a4 = (float*)sym(g_a4);
    float* a5 = (float*)sym(g_a5);
    float* wc1 = (float*)sym(g_wc1);
    float* wc2 = (float*)sym(g_wc2);
    float* wc3 = (float*)sym(g_wc3);
    unsigned short* wH4 = (unsigned short*)sym(g_wH4);
    unsigned short* wL4 = (unsigned short*)sym(g_wL4);
    unsigned short* wH5 = (unsigned short*)sym(g_wH5);
    unsigned short* wL5 = (unsigned short*)sym(g_wL5);
    float* s1 = (float*)sym(g_s1);
    float* s2 = (float*)sym(g_s2);
    float* s3 = (float*)sym(g_s3);
    float* s4 = (float*)sym(g_s4);
    float* s5 = (float*)sym(g_s5);

    // dynamic smem for HMMA kernels: 4 arrays of 64*264 bf16 = 135168 B
    constexpr int MMA_SMEM = 4 * 64 * 264 * 2;
    cudaFuncSetAttribute(upconv_mma<64, 64>,
                         cudaFuncAttributeMaxDynamicSharedMemorySize, MMA_SMEM);
    cudaFuncSetAttribute(upconv_mma<128, 128>,
                         cudaFuncAttributeMaxDynamicSharedMemorySize, MMA_SMEM);

    // fused prologue
    {
        int ntot = N1 + N2 + N3;
        combine_all<<<(ntot + 255) / 256, 256>>>(w1, wc1, w2, wc2, w3, wc3);
        build_wHL<<<(2 * 4096 + 255) / 256, 256>>>(w4, w5, wH4, wL4, wH5, wL5);
        int warps = B_ * 576;
        style_all<<<(warps * 32 + 255) / 256, 256>>>(style,
                                                     fw1, fb1, s1, fw2, fb2, s2,
                                                     fw3, fb3, s3, fw4, fb4, s4,
                                                     fw5, fb5, s5);
    }

    // L1: 512->256, 8x8 -> 16x16 (scalar)
    upconv<512, 256, 8, 8, 8, 2, 8><<<dim3(1, 1, B_ * 16), dim3(32, 8)>>>(x, wc1, s1, a1);
    // L2: 256->128, 16 -> 32 (scalar)
    upconv<256, 128, 16, 16, 16, 2, 8><<<dim3(1, 4, B_ * 8), dim3(32, 8)>>>(a1, wc2, s2, a2);
    // L3: 128->64, 32 -> 64 (scalar)
    upconv<128, 64, 32, 32, 32, 4, 4><<<dim3(1, 16, B_ * 4), dim3(32, 4)>>>(a2, wc3, s3, a3);
    // L4: 64->64, 64 -> 128 (HMMA)
    upconv_mma<64, 64><<<dim3(8, 8, B_ * 4), 256, MMA_SMEM>>>(a3, wH4, wL4, s4, a4);
    // L5: 64->64, 128 -> 256 (HMMA)
    upconv_mma<128, 128><<<dim3(16, 16, B_ * 4), 256, MMA_SMEM>>>(a4, wH5, wL5, s5, a5);

    // final conv 64 -> 3 + bias
    final_conv<<<dim3(8, 8, B_), 256>>>(a5, wf, bf, (float*)d_out);
}